// round 1
// baseline (speedup 1.0000x reference)
#include <cuda_runtime.h>
#include <math.h>

// Problem constants (fixed by the reference)
#define BATCH 2
#define SEQ   2048
#define DIM   1024
#define NH    16
#define HD    64
#define BT    (BATCH*SEQ)      // 4096
#define QKVN  (3*DIM)          // 3072

// Scratch (static device arrays; no allocations allowed)
__device__ float g_q[BATCH*NH*SEQ*HD];     // [B,H,T,D]
__device__ float g_k[BATCH*NH*SEQ*HD];
__device__ float g_v[BATCH*NH*SEQ*HD];
__device__ float g_attn[BT*DIM];           // [B*T, C] for proj GEMM

// ---------------------------------------------------------------------------
// 128x128x8 double-buffered fp32 SGEMM, 256 threads, 8x8 per thread.
// MODE 0: epilogue scatters QKV columns into g_q/g_k/g_v [B,H,T,D] + bias
// MODE 1: plain C[row*N+col] = acc + bias[col]
// A: [M,K] row-major, B: [K,N] row-major.
// ---------------------------------------------------------------------------
template<int MODE>
__global__ __launch_bounds__(256, 2)
void sgemm_kernel(const float* __restrict__ A, const float* __restrict__ B,
                  const float* __restrict__ bias, float* __restrict__ C,
                  int M, int N, int K,
                  float* __restrict__ oq, float* __restrict__ ok, float* __restrict__ ov)
{
    __shared__ float As[2][8][128];
    __shared__ float Bs[2][8][128];

    const int tid = threadIdx.x;
    const int tx = tid & 15;          // 0..15 -> col group
    const int ty = tid >> 4;          // 0..15 -> row group

    const int aRow = tid >> 1;        // 0..127
    const int aK   = (tid & 1) * 4;   // 0 or 4
    const int bK   = tid >> 5;        // 0..7
    const int bCol = (tid & 31) * 4;  // 0..124

    const float* Ap = A + (size_t)((blockIdx.y << 7) + aRow) * K + aK;
    const float* Bp = B + (size_t)bK * N + (blockIdx.x << 7) + bCol;

    float acc[8][8];
#pragma unroll
    for (int i = 0; i < 8; i++)
#pragma unroll
        for (int j = 0; j < 8; j++) acc[i][j] = 0.f;

    // preload tile 0
    float4 ra = *(const float4*)Ap;
    float4 rb = *(const float4*)Bp;
    As[0][aK+0][aRow] = ra.x; As[0][aK+1][aRow] = ra.y;
    As[0][aK+2][aRow] = ra.z; As[0][aK+3][aRow] = ra.w;
    *(float4*)&Bs[0][bK][bCol] = rb;
    __syncthreads();

    const int tiles = K >> 3;
    for (int t = 0; t < tiles; ++t) {
        const int buf = t & 1;
        float4 na, nb;
        const bool more = (t + 1 < tiles);
        if (more) {
            na = *(const float4*)(Ap + (t + 1) * 8);
            nb = *(const float4*)(Bp + (size_t)(t + 1) * 8 * N);
        }
#pragma unroll
        for (int kk = 0; kk < 8; ++kk) {
            float4 a0 = *(const float4*)&As[buf][kk][ty * 8];
            float4 a1 = *(const float4*)&As[buf][kk][ty * 8 + 4];
            float4 b0 = *(const float4*)&Bs[buf][kk][tx * 8];
            float4 b1 = *(const float4*)&Bs[buf][kk][tx * 8 + 4];
            float av[8] = {a0.x,a0.y,a0.z,a0.w,a1.x,a1.y,a1.z,a1.w};
            float bv[8] = {b0.x,b0.y,b0.z,b0.w,b1.x,b1.y,b1.z,b1.w};
#pragma unroll
            for (int i = 0; i < 8; i++)
#pragma unroll
                for (int j = 0; j < 8; j++)
                    acc[i][j] = fmaf(av[i], bv[j], acc[i][j]);
        }
        if (more) {
            const int nbuf = buf ^ 1;
            As[nbuf][aK+0][aRow] = na.x; As[nbuf][aK+1][aRow] = na.y;
            As[nbuf][aK+2][aRow] = na.z; As[nbuf][aK+3][aRow] = na.w;
            *(float4*)&Bs[nbuf][bK][bCol] = nb;
        }
        __syncthreads();
    }

    const int rowBase = (blockIdx.y << 7) + ty * 8;
    const int colBase = (blockIdx.x << 7) + tx * 8;
#pragma unroll
    for (int i = 0; i < 8; i++) {
        const int row = rowBase + i;
#pragma unroll
        for (int j = 0; j < 8; j++) {
            const int col = colBase + j;
            float val = acc[i][j] + bias[col];
            if (MODE == 0) {
                // col in [0,3072): sel*1024 + h*64 + d ; row = b*2048 + t
                const int sel = col >> 10;
                const int c   = col & 1023;
                const int h   = c >> 6;
                const int d   = c & 63;
                const int b_  = row >> 11;
                const int t_  = row & 2047;
                const int idx = (((b_ * NH + h) * SEQ) + t_) * HD + d;
                float* dst = (sel == 0) ? oq : (sel == 1) ? ok : ov;
                dst[idx] = val;
            } else {
                C[(size_t)row * N + col] = val;
            }
        }
    }
}

// ---------------------------------------------------------------------------
// Flash attention, fp32. Br=Bc=64, D=64, 128 threads (16x8 thread grid).
// Each thread: 8 S-rows x 4 S-cols. Online softmax via shfl over the 16
// col-threads of a row (lane%16 group within a warp).
// smem (dynamic): Qt[64][68] (d-major), Kt[64][68] (d-major),
//                 Vs[64][68] (t-major), Ps[64][68] (r-major). 69632 B.
// ---------------------------------------------------------------------------
#define APAD 68
#define ATTN_SMEM (4 * 64 * APAD * 4)

__global__ __launch_bounds__(128)
void attn_kernel(const float* __restrict__ q, const float* __restrict__ k,
                 const float* __restrict__ v, float* __restrict__ out)
{
    extern __shared__ float sm[];
    float* Qt = sm;
    float* Kt = Qt + 64 * APAD;
    float* Vs = Kt + 64 * APAD;
    float* Ps = Vs + 64 * APAD;

    const int tid = threadIdx.x;
    const int tx = tid & 15;   // col group: cols tx*4 .. tx*4+3
    const int ty = tid >> 4;   // row group: rows ty*8 .. ty*8+7

    const int bh = blockIdx.y;                        // 0..31
    const int qb = (gridDim.x - 1) - blockIdx.x;      // big tiles first
    const int b_ = bh >> 4;
    const int h  = bh & 15;

    // Load Q tile transposed: Qt[d][r]
    {
        const size_t base = ((size_t)bh * SEQ + qb * 64) * HD;
        for (int idx = tid; idx < 64 * 16; idx += 128) {
            const int r = idx >> 4, s = idx & 15;
            float4 val = *(const float4*)&q[base + r * HD + s * 4];
            Qt[(s*4+0)*APAD + r] = val.x;
            Qt[(s*4+1)*APAD + r] = val.y;
            Qt[(s*4+2)*APAD + r] = val.z;
            Qt[(s*4+3)*APAD + r] = val.w;
        }
    }

    float m[8], l[8], O[8][4];
#pragma unroll
    for (int i = 0; i < 8; i++) {
        m[i] = -INFINITY; l[i] = 0.f;
#pragma unroll
        for (int j = 0; j < 4; j++) O[i][j] = 0.f;
    }

    for (int kb = 0; kb <= qb; ++kb) {
        __syncthreads();  // previous PV done (and Q load visible on iter 0)
        // load K (transposed, d-major) and V (t-major)
        {
            const size_t base = ((size_t)bh * SEQ + kb * 64) * HD;
            for (int idx = tid; idx < 64 * 16; idx += 128) {
                const int r = idx >> 4, s = idx & 15;
                float4 kv = *(const float4*)&k[base + r * HD + s * 4];
                Kt[(s*4+0)*APAD + r] = kv.x;
                Kt[(s*4+1)*APAD + r] = kv.y;
                Kt[(s*4+2)*APAD + r] = kv.z;
                Kt[(s*4+3)*APAD + r] = kv.w;
                float4 vv = *(const float4*)&v[base + r * HD + s * 4];
                *(float4*)&Vs[r * APAD + s * 4] = vv;
            }
        }
        __syncthreads();

        // S = Q @ K^T  (8x4 per thread)
        float s_[8][4];
#pragma unroll
        for (int i = 0; i < 8; i++)
#pragma unroll
            for (int j = 0; j < 4; j++) s_[i][j] = 0.f;

#pragma unroll 4
        for (int d = 0; d < 64; ++d) {
            float4 a0 = *(const float4*)&Qt[d * APAD + ty * 8];
            float4 a1 = *(const float4*)&Qt[d * APAD + ty * 8 + 4];
            float4 bb = *(const float4*)&Kt[d * APAD + tx * 4];
            float av[8] = {a0.x,a0.y,a0.z,a0.w,a1.x,a1.y,a1.z,a1.w};
            float bv[4] = {bb.x,bb.y,bb.z,bb.w};
#pragma unroll
            for (int i = 0; i < 8; i++)
#pragma unroll
                for (int j = 0; j < 4; j++)
                    s_[i][j] = fmaf(av[i], bv[j], s_[i][j]);
        }

        const float scale = 0.125f;  // 1/sqrt(64)
        if (kb == qb) {
#pragma unroll
            for (int i = 0; i < 8; i++) {
                const int rr = ty * 8 + i;
#pragma unroll
                for (int j = 0; j < 4; j++) {
                    const int cc = tx * 4 + j;
                    s_[i][j] = (cc > rr) ? -INFINITY : s_[i][j] * scale;
                }
            }
        } else {
#pragma unroll
            for (int i = 0; i < 8; i++)
#pragma unroll
                for (int j = 0; j < 4; j++) s_[i][j] *= scale;
        }

        // Online softmax per row
#pragma unroll
        for (int i = 0; i < 8; i++) {
            float mx = s_[i][0];
#pragma unroll
            for (int j = 1; j < 4; j++) mx = fmaxf(mx, s_[i][j]);
#pragma unroll
            for (int off = 1; off < 16; off <<= 1)
                mx = fmaxf(mx, __shfl_xor_sync(0xffffffffu, mx, off));
            const float mn = fmaxf(m[i], mx);
            const float alpha = __expf(m[i] - mn);
            m[i] = mn;
            float rs = 0.f;
#pragma unroll
            for (int j = 0; j < 4; j++) {
                const float p = __expf(s_[i][j] - mn);
                s_[i][j] = p;
                rs += p;
            }
#pragma unroll
            for (int off = 1; off < 16; off <<= 1)
                rs += __shfl_xor_sync(0xffffffffu, rs, off);
            l[i] = l[i] * alpha + rs;
#pragma unroll
            for (int j = 0; j < 4; j++) O[i][j] *= alpha;
            *(float4*)&Ps[(ty * 8 + i) * APAD + tx * 4] =
                make_float4(s_[i][0], s_[i][1], s_[i][2], s_[i][3]);
        }
        __syncthreads();

        // O += P @ V
#pragma unroll 4
        for (int kk = 0; kk < 64; ++kk) {
            float4 vv = *(const float4*)&Vs[kk * APAD + tx * 4];
#pragma unroll
            for (int i = 0; i < 8; i++) {
                const float p = Ps[(ty * 8 + i) * APAD + kk];
                O[i][0] = fmaf(p, vv.x, O[i][0]);
                O[i][1] = fmaf(p, vv.y, O[i][1]);
                O[i][2] = fmaf(p, vv.z, O[i][2]);
                O[i][3] = fmaf(p, vv.w, O[i][3]);
            }
        }
    }

    // Write normalized O to g_attn [B*T, C], C index = h*64 + c
#pragma unroll
    for (int i = 0; i < 8; i++) {
        const float inv = 1.f / l[i];
        const int t_ = qb * 64 + ty * 8 + i;
        const size_t o = ((size_t)(b_ * SEQ + t_)) * DIM + h * HD + tx * 4;
        *(float4*)&out[o] = make_float4(O[i][0]*inv, O[i][1]*inv, O[i][2]*inv, O[i][3]*inv);
    }
}

// ---------------------------------------------------------------------------
extern "C" void kernel_launch(void* const* d_in, const int* in_sizes, int n_in,
                              void* d_out, int out_size)
{
    const float* x     = (const float*)d_in[0];
    const float* Wqkv  = (const float*)d_in[1];
    const float* bqkv  = (const float*)d_in[2];
    const float* Wproj = (const float*)d_in[3];
    const float* bproj = (const float*)d_in[4];
    // d_in[5] = mask (causal, known statically) — unused
    float* out = (float*)d_out;

    float *gq, *gk, *gv, *gattn;
    cudaGetSymbolAddress((void**)&gq, g_q);
    cudaGetSymbolAddress((void**)&gk, g_k);
    cudaGetSymbolAddress((void**)&gv, g_v);
    cudaGetSymbolAddress((void**)&gattn, g_attn);

    cudaFuncSetAttribute(attn_kernel, cudaFuncAttributeMaxDynamicSharedMemorySize, ATTN_SMEM);

    // 1) QKV projection + head scatter
    {
        dim3 grid(QKVN / 128, BT / 128);   // (24, 32)
        sgemm_kernel<0><<<grid, 256>>>(x, Wqkv, bqkv, nullptr,
                                       BT, QKVN, DIM, gq, gk, gv);
    }
    // 2) Causal flash attention
    {
        dim3 grid(SEQ / 64, BATCH * NH);   // (32, 32)
        attn_kernel<<<grid, 128, ATTN_SMEM>>>(gq, gk, gv, gattn);
    }
    // 3) Output projection
    {
        dim3 grid(DIM / 128, BT / 128);    // (8, 32)
        sgemm_kernel<1><<<grid, 256>>>(gattn, Wproj, bproj, out,
                                       BT, DIM, DIM, nullptr, nullptr, nullptr);
    }
    (void)in_sizes; (void)n_in; (void)out_size;
}

// round 2
// speedup vs baseline: 2.4316x; 2.4316x over previous
#include <cuda_runtime.h>
#include <math.h>
#include <stdint.h>

#define BATCH 2
#define SEQ   2048
#define DIM   1024
#define NH    16
#define HD    64
#define BT    (BATCH*SEQ)      // 4096
#define QKVN  (3*DIM)          // 3072

// Scratch (static device arrays; no allocations allowed)
__device__ float g_q[BATCH*NH*SEQ*HD];     // [B,H,T,D]
__device__ float g_k[BATCH*NH*SEQ*HD];
__device__ float g_v[BATCH*NH*SEQ*HD];
__device__ float g_attn[BT*DIM];           // [B*T, C] for proj GEMM

__device__ __forceinline__ uint32_t f2tf(float f) {
    uint32_t u;
    asm("cvt.rna.tf32.f32 %0, %1;" : "=r"(u) : "f"(f));
    return u;
}

// D += A*B  (m16n8k8, tf32 in, fp32 accum)
__device__ __forceinline__ void mma8(float* c, const uint32_t* a, uint32_t b0, uint32_t b1) {
    asm volatile(
        "mma.sync.aligned.m16n8k8.row.col.f32.tf32.tf32.f32 "
        "{%0,%1,%2,%3},{%4,%5,%6,%7},{%8,%9},{%0,%1,%2,%3};\n"
        : "+f"(c[0]), "+f"(c[1]), "+f"(c[2]), "+f"(c[3])
        : "r"(a[0]), "r"(a[1]), "r"(a[2]), "r"(a[3]), "r"(b0), "r"(b1));
}

// ---------------------------------------------------------------------------
// TF32 tensor-core GEMM: 128x128 tile, BK=16, 256 threads (8 warps of 32x64).
// A [M,K] row-major, B [K,N] row-major. Smem k-major, pad 136 (conflict-free).
// MODE 0: scatter QKV epilogue; MODE 1: plain C = acc + bias.
// ---------------------------------------------------------------------------
#define GPAD 136

template<int MODE>
__global__ __launch_bounds__(256)
void gemm_tf32(const float* __restrict__ A, const float* __restrict__ B,
               const float* __restrict__ bias, float* __restrict__ C,
               int M, int N, int K,
               float* __restrict__ oq, float* __restrict__ ok, float* __restrict__ ov)
{
    __shared__ uint32_t As[2][16][GPAD];
    __shared__ uint32_t Bs[2][16][GPAD];

    const int tid  = threadIdx.x;
    const int lane = tid & 31;
    const int wid  = tid >> 5;
    const int g    = lane >> 2;     // 0..7
    const int tg   = lane & 3;      // 0..3
    const int warp_m = (wid & 3) * 32;   // 4 warp rows
    const int warp_n = (wid >> 2) * 64;  // 2 warp cols

    // staging indices
    const int aM  = tid >> 1;            // 0..127
    const int aK0 = (tid & 1) * 8;       // 0 or 8
    const int bK  = tid >> 4;            // 0..15
    const int bN0 = (tid & 15) * 8;      // 0..120

    const float* Ap = A + (size_t)(blockIdx.y * 128 + aM) * K + aK0;
    const float* Bp = B + (size_t)bK * N + blockIdx.x * 128 + bN0;

    float acc[2][8][4];
#pragma unroll
    for (int mt = 0; mt < 2; mt++)
#pragma unroll
        for (int nt = 0; nt < 8; nt++)
#pragma unroll
            for (int i = 0; i < 4; i++) acc[mt][nt][i] = 0.f;

    // preload tile 0
    float4 ra0 = *(const float4*)Ap;
    float4 ra1 = *(const float4*)(Ap + 4);
    float4 rb0 = *(const float4*)Bp;
    float4 rb1 = *(const float4*)(Bp + 4);

    {
        As[0][aK0+0][aM] = f2tf(ra0.x); As[0][aK0+1][aM] = f2tf(ra0.y);
        As[0][aK0+2][aM] = f2tf(ra0.z); As[0][aK0+3][aM] = f2tf(ra0.w);
        As[0][aK0+4][aM] = f2tf(ra1.x); As[0][aK0+5][aM] = f2tf(ra1.y);
        As[0][aK0+6][aM] = f2tf(ra1.z); As[0][aK0+7][aM] = f2tf(ra1.w);
        uint4 u0 = { f2tf(rb0.x), f2tf(rb0.y), f2tf(rb0.z), f2tf(rb0.w) };
        uint4 u1 = { f2tf(rb1.x), f2tf(rb1.y), f2tf(rb1.z), f2tf(rb1.w) };
        *(uint4*)&Bs[0][bK][bN0]     = u0;
        *(uint4*)&Bs[0][bK][bN0 + 4] = u1;
    }
    __syncthreads();

    const int tiles = K >> 4;   // K/16
    for (int t = 0; t < tiles; ++t) {
        const int buf = t & 1;
        const bool more = (t + 1 < tiles);
        if (more) {
            ra0 = *(const float4*)(Ap + (t + 1) * 16);
            ra1 = *(const float4*)(Ap + (t + 1) * 16 + 4);
            rb0 = *(const float4*)(Bp + (size_t)(t + 1) * 16 * N);
            rb1 = *(const float4*)(Bp + (size_t)(t + 1) * 16 * N + 4);
        }

#pragma unroll
        for (int ks = 0; ks < 2; ++ks) {
            const int kb = ks * 8;
            uint32_t afr[2][4];
#pragma unroll
            for (int mt = 0; mt < 2; mt++) {
                const int r = warp_m + mt * 16 + g;
                afr[mt][0] = As[buf][kb + tg][r];
                afr[mt][1] = As[buf][kb + tg][r + 8];
                afr[mt][2] = As[buf][kb + tg + 4][r];
                afr[mt][3] = As[buf][kb + tg + 4][r + 8];
            }
            uint32_t bfr[8][2];
#pragma unroll
            for (int nt = 0; nt < 8; nt++) {
                const int c = warp_n + nt * 8 + g;
                bfr[nt][0] = Bs[buf][kb + tg][c];
                bfr[nt][1] = Bs[buf][kb + tg + 4][c];
            }
#pragma unroll
            for (int mt = 0; mt < 2; mt++)
#pragma unroll
                for (int nt = 0; nt < 8; nt++)
                    mma8(acc[mt][nt], afr[mt], bfr[nt][0], bfr[nt][1]);
        }

        if (more) {
            const int nb = buf ^ 1;
            As[nb][aK0+0][aM] = f2tf(ra0.x); As[nb][aK0+1][aM] = f2tf(ra0.y);
            As[nb][aK0+2][aM] = f2tf(ra0.z); As[nb][aK0+3][aM] = f2tf(ra0.w);
            As[nb][aK0+4][aM] = f2tf(ra1.x); As[nb][aK0+5][aM] = f2tf(ra1.y);
            As[nb][aK0+6][aM] = f2tf(ra1.z); As[nb][aK0+7][aM] = f2tf(ra1.w);
            uint4 u0 = { f2tf(rb0.x), f2tf(rb0.y), f2tf(rb0.z), f2tf(rb0.w) };
            uint4 u1 = { f2tf(rb1.x), f2tf(rb1.y), f2tf(rb1.z), f2tf(rb1.w) };
            *(uint4*)&Bs[nb][bK][bN0]     = u0;
            *(uint4*)&Bs[nb][bK][bN0 + 4] = u1;
        }
        __syncthreads();
    }

    // epilogue
    const int rowB = blockIdx.y * 128 + warp_m;
    const int colB = blockIdx.x * 128 + warp_n;
#pragma unroll
    for (int mt = 0; mt < 2; mt++) {
#pragma unroll
        for (int nt = 0; nt < 8; nt++) {
            const int r = rowB + mt * 16 + g;
            const int c = colB + nt * 8 + 2 * tg;
            const float bv0 = bias[c], bv1 = bias[c + 1];
            float v00 = acc[mt][nt][0] + bv0;
            float v01 = acc[mt][nt][1] + bv1;
            float v10 = acc[mt][nt][2] + bv0;
            float v11 = acc[mt][nt][3] + bv1;
            if (MODE == 0) {
                const int sel = c >> 10;
                const int cc  = c & 1023;
                const int h   = cc >> 6;
                const int d   = cc & 63;
                float* dst = (sel == 0) ? oq : (sel == 1) ? ok : ov;
                {
                    const int b_ = r >> 11, t_ = r & 2047;
                    const size_t idx = (((size_t)(b_ * NH + h) * SEQ) + t_) * HD + d;
                    *(float2*)&dst[idx] = make_float2(v00, v01);
                }
                {
                    const int r2 = r + 8;
                    const int b_ = r2 >> 11, t_ = r2 & 2047;
                    const size_t idx = (((size_t)(b_ * NH + h) * SEQ) + t_) * HD + d;
                    *(float2*)&dst[idx] = make_float2(v10, v11);
                }
            } else {
                *(float2*)&C[(size_t)r * N + c]       = make_float2(v00, v01);
                *(float2*)&C[(size_t)(r + 8) * N + c] = make_float2(v10, v11);
            }
        }
    }
}

// ---------------------------------------------------------------------------
// Flash attention with tf32 tensor cores.
// Br=Bc=64, 128 threads (4 warps x 16 rows). Q pre-scaled by 1/8, A-frags in
// registers across the whole KV loop. smem: QP[64][68] (Q then reused for P),
// Ks[64][72], Vs[64][72], all tf32 (u32).
// ---------------------------------------------------------------------------
#define QPPAD 68
#define KVPAD 72
#define ATTN_SMEM ((64*QPPAD + 2*64*KVPAD) * 4)

__global__ __launch_bounds__(128)
void attn_tf32(const float* __restrict__ q, const float* __restrict__ k,
               const float* __restrict__ v, float* __restrict__ out)
{
    extern __shared__ uint32_t sm[];
    uint32_t* QP = sm;                   // [64][68]
    uint32_t* Ks = QP + 64 * QPPAD;      // [64][72]
    uint32_t* Vs = Ks + 64 * KVPAD;      // [64][72]

    const int tid  = threadIdx.x;
    const int lane = tid & 31;
    const int wid  = tid >> 5;          // 0..3
    const int g    = lane >> 2;         // 0..7
    const int tg   = lane & 3;          // 0..3
    const int wbase = wid * 16;

    const int bh = blockIdx.y;                    // 0..31
    const int qb = (gridDim.x - 1) - blockIdx.x;  // big tiles first
    const int b_ = bh >> 4;
    const int h  = bh & 15;

    // stage Q (scaled by 1/sqrt(64) = 0.125), tf32
    {
        const size_t base = ((size_t)bh * SEQ + (size_t)qb * 64) * HD;
        for (int idx = tid; idx < 64 * 16; idx += 128) {
            const int r = idx >> 4, s = idx & 15;
            float4 val = *(const float4*)&q[base + r * HD + s * 4];
            uint4 u = { f2tf(val.x * 0.125f), f2tf(val.y * 0.125f),
                        f2tf(val.z * 0.125f), f2tf(val.w * 0.125f) };
            *(uint4*)&QP[r * QPPAD + s * 4] = u;
        }
    }
    __syncthreads();

    // Q fragments in registers (rows wbase..wbase+15, all 8 k-slices)
    uint32_t qf[8][4];
#pragma unroll
    for (int kt = 0; kt < 8; kt++) {
        const int r0 = wbase + g;
        qf[kt][0] = QP[r0 * QPPAD + kt * 8 + tg];
        qf[kt][1] = QP[(r0 + 8) * QPPAD + kt * 8 + tg];
        qf[kt][2] = QP[r0 * QPPAD + kt * 8 + tg + 4];
        qf[kt][3] = QP[(r0 + 8) * QPPAD + kt * 8 + tg + 4];
    }

    float m0 = -INFINITY, m1 = -INFINITY, l0 = 0.f, l1 = 0.f;
    float O[8][4];
#pragma unroll
    for (int nt = 0; nt < 8; nt++)
#pragma unroll
        for (int i = 0; i < 4; i++) O[nt][i] = 0.f;

    for (int kb = 0; kb <= qb; ++kb) {
        __syncthreads();   // prev PV done reading Vs; all Q-frag reads done (kb=0)

        // stage K,V tiles (tf32)
        {
            const size_t base = ((size_t)bh * SEQ + (size_t)kb * 64) * HD;
            for (int idx = tid; idx < 64 * 16; idx += 128) {
                const int r = idx >> 4, s = idx & 15;
                float4 kv = *(const float4*)&k[base + r * HD + s * 4];
                uint4 uk = { f2tf(kv.x), f2tf(kv.y), f2tf(kv.z), f2tf(kv.w) };
                *(uint4*)&Ks[r * KVPAD + s * 4] = uk;
                float4 vv = *(const float4*)&v[base + r * HD + s * 4];
                uint4 uv = { f2tf(vv.x), f2tf(vv.y), f2tf(vv.z), f2tf(vv.w) };
                *(uint4*)&Vs[r * KVPAD + s * 4] = uv;
            }
        }
        __syncthreads();

        // S = Qs @ K^T   (16 rows x 64 cols per warp)
        float s_[8][4];
#pragma unroll
        for (int nt = 0; nt < 8; nt++)
#pragma unroll
            for (int i = 0; i < 4; i++) s_[nt][i] = 0.f;

#pragma unroll
        for (int kt = 0; kt < 8; kt++) {
#pragma unroll
            for (int nt = 0; nt < 8; nt++) {
                const int trow = nt * 8 + g;
                uint32_t b0 = Ks[trow * KVPAD + kt * 8 + tg];
                uint32_t b1 = Ks[trow * KVPAD + kt * 8 + tg + 4];
                mma8(s_[nt], qf[kt], b0, b1);
            }
        }

        // causal mask on the diagonal tile
        if (kb == qb) {
#pragma unroll
            for (int nt = 0; nt < 8; nt++) {
                const int cc = nt * 8 + 2 * tg;
                const int rr = wbase + g;
                if (cc > rr)     s_[nt][0] = -INFINITY;
                if (cc + 1 > rr) s_[nt][1] = -INFINITY;
                if (cc > rr + 8)     s_[nt][2] = -INFINITY;
                if (cc + 1 > rr + 8) s_[nt][3] = -INFINITY;
            }
        }

        // online softmax (rows g and g+8 of this warp's strip)
        float mx0 = -INFINITY, mx1 = -INFINITY;
#pragma unroll
        for (int nt = 0; nt < 8; nt++) {
            mx0 = fmaxf(mx0, fmaxf(s_[nt][0], s_[nt][1]));
            mx1 = fmaxf(mx1, fmaxf(s_[nt][2], s_[nt][3]));
        }
#pragma unroll
        for (int off = 1; off < 4; off <<= 1) {
            mx0 = fmaxf(mx0, __shfl_xor_sync(0xffffffffu, mx0, off));
            mx1 = fmaxf(mx1, __shfl_xor_sync(0xffffffffu, mx1, off));
        }
        const float mn0 = fmaxf(m0, mx0);
        const float mn1 = fmaxf(m1, mx1);
        const float al0 = __expf(m0 - mn0);
        const float al1 = __expf(m1 - mn1);
        m0 = mn0; m1 = mn1;

        float rs0 = 0.f, rs1 = 0.f;
#pragma unroll
        for (int nt = 0; nt < 8; nt++) {
            s_[nt][0] = __expf(s_[nt][0] - mn0); rs0 += s_[nt][0];
            s_[nt][1] = __expf(s_[nt][1] - mn0); rs0 += s_[nt][1];
            s_[nt][2] = __expf(s_[nt][2] - mn1); rs1 += s_[nt][2];
            s_[nt][3] = __expf(s_[nt][3] - mn1); rs1 += s_[nt][3];
        }
#pragma unroll
        for (int off = 1; off < 4; off <<= 1) {
            rs0 += __shfl_xor_sync(0xffffffffu, rs0, off);
            rs1 += __shfl_xor_sync(0xffffffffu, rs1, off);
        }
        l0 = l0 * al0 + rs0;
        l1 = l1 * al1 + rs1;
#pragma unroll
        for (int nt = 0; nt < 8; nt++) {
            O[nt][0] *= al0; O[nt][1] *= al0;
            O[nt][2] *= al1; O[nt][3] *= al1;
        }

        // write P (tf32) into QP buffer (own warp's 16 rows only)
#pragma unroll
        for (int nt = 0; nt < 8; nt++) {
            const int rr = wbase + g;
            const int cc = nt * 8 + 2 * tg;
            QP[rr * QPPAD + cc]           = f2tf(s_[nt][0]);
            QP[rr * QPPAD + cc + 1]       = f2tf(s_[nt][1]);
            QP[(rr + 8) * QPPAD + cc]     = f2tf(s_[nt][2]);
            QP[(rr + 8) * QPPAD + cc + 1] = f2tf(s_[nt][3]);
        }
        __syncwarp();   // P read back only by this warp's lanes

        // O += P @ V
#pragma unroll
        for (int kt = 0; kt < 8; kt++) {
            uint32_t pa[4];
            pa[0] = QP[(wbase + g) * QPPAD + kt * 8 + tg];
            pa[1] = QP[(wbase + g + 8) * QPPAD + kt * 8 + tg];
            pa[2] = QP[(wbase + g) * QPPAD + kt * 8 + tg + 4];
            pa[3] = QP[(wbase + g + 8) * QPPAD + kt * 8 + tg + 4];
#pragma unroll
            for (int nt = 0; nt < 8; nt++) {
                uint32_t b0 = Vs[(kt * 8 + tg) * KVPAD + nt * 8 + g];
                uint32_t b1 = Vs[(kt * 8 + tg + 4) * KVPAD + nt * 8 + g];
                mma8(O[nt], pa, b0, b1);
            }
        }
    }

    // normalize and write to g_attn [B*T, C]
    const float inv0 = 1.f / l0;
    const float inv1 = 1.f / l1;
    const int t0 = qb * 64 + wbase + g;
#pragma unroll
    for (int nt = 0; nt < 8; nt++) {
        const int c = h * HD + nt * 8 + 2 * tg;
        *(float2*)&out[((size_t)(b_ * SEQ + t0)) * DIM + c] =
            make_float2(O[nt][0] * inv0, O[nt][1] * inv0);
        *(float2*)&out[((size_t)(b_ * SEQ + t0 + 8)) * DIM + c] =
            make_float2(O[nt][2] * inv1, O[nt][3] * inv1);
    }
}

// ---------------------------------------------------------------------------
extern "C" void kernel_launch(void* const* d_in, const int* in_sizes, int n_in,
                              void* d_out, int out_size)
{
    const float* x     = (const float*)d_in[0];
    const float* Wqkv  = (const float*)d_in[1];
    const float* bqkv  = (const float*)d_in[2];
    const float* Wproj = (const float*)d_in[3];
    const float* bproj = (const float*)d_in[4];
    // d_in[5] = causal mask (static) — unused
    float* out = (float*)d_out;

    float *gq, *gk, *gv, *gattn;
    cudaGetSymbolAddress((void**)&gq, g_q);
    cudaGetSymbolAddress((void**)&gk, g_k);
    cudaGetSymbolAddress((void**)&gv, g_v);
    cudaGetSymbolAddress((void**)&gattn, g_attn);

    cudaFuncSetAttribute(attn_tf32, cudaFuncAttributeMaxDynamicSharedMemorySize, ATTN_SMEM);

    // 1) QKV projection + head scatter
    {
        dim3 grid(QKVN / 128, BT / 128);   // (24, 32)
        gemm_tf32<0><<<grid, 256>>>(x, Wqkv, bqkv, nullptr,
                                    BT, QKVN, DIM, gq, gk, gv);
    }
    // 2) Causal flash attention (tensor cores)
    {
        dim3 grid(SEQ / 64, BATCH * NH);   // (32, 32)
        attn_tf32<<<grid, 128, ATTN_SMEM>>>(gq, gk, gv, gattn);
    }
    // 3) Output projection
    {
        dim3 grid(DIM / 128, BT / 128);    // (8, 32)
        gemm_tf32<1><<<grid, 256>>>(gattn, Wproj, bproj, out,
                                    BT, DIM, DIM, nullptr, nullptr, nullptr);
    }
    (void)in_sizes; (void)n_in; (void)out_size;
}

// round 4
// speedup vs baseline: 2.8351x; 1.1659x over previous
#include <cuda_runtime.h>
#include <math.h>
#include <stdint.h>

#define BATCH 2
#define SEQ   2048
#define DIM   1024
#define NH    16
#define HD    64
#define BT    (BATCH*SEQ)      // 4096
#define QKVN  (3*DIM)          // 3072

// Scratch (static device arrays; no allocations allowed)
__device__ float    g_q[BATCH*NH*SEQ*HD];     // [B,H,T,D]  (tf32-rounded bits)
__device__ float    g_k[BATCH*NH*SEQ*HD];
__device__ float    g_v[BATCH*NH*SEQ*HD];
__device__ float    g_attn[BT*DIM];           // [B*T, C]   (tf32-rounded bits)
__device__ uint32_t g_xt[BT*DIM];             // tf32(x)
__device__ uint32_t g_wqkvt[DIM*QKVN];        // tf32(W_qkv)
__device__ uint32_t g_wprojt[DIM*DIM];        // tf32(W_proj)

// ---------------------------------------------------------------------------
__device__ __forceinline__ uint32_t f2tf(float f) {
    uint32_t u;
    asm("cvt.rna.tf32.f32 %0, %1;" : "=r"(u) : "f"(f));
    return u;
}
__device__ __forceinline__ uint32_t smem_u32(const void* p) {
    uint32_t a;
    asm("{ .reg .u64 t; cvta.to.shared.u64 t, %1; cvt.u32.u64 %0, t; }" : "=r"(a) : "l"(p));
    return a;
}
#define CP16(dst, src) \
    asm volatile("cp.async.cg.shared.global [%0], [%1], 16;" :: "r"(dst), "l"(src) : "memory")
#define CPCOMMIT() asm volatile("cp.async.commit_group;" ::: "memory")
#define CPWAIT(n)  asm volatile("cp.async.wait_group %0;" :: "n"(n) : "memory")

// m16n8k8 tf32 mma, fp32 accum
__device__ __forceinline__ void mma8(float* c, const uint32_t* a, uint32_t b0, uint32_t b1) {
    asm volatile(
        "mma.sync.aligned.m16n8k8.row.col.f32.tf32.tf32.f32 "
        "{%0,%1,%2,%3},{%4,%5,%6,%7},{%8,%9},{%0,%1,%2,%3};\n"
        : "+f"(c[0]), "+f"(c[1]), "+f"(c[2]), "+f"(c[3])
        : "r"(a[0]), "r"(a[1]), "r"(a[2]), "r"(a[3]), "r"(b0), "r"(b1));
}

// ---------------------------------------------------------------------------
// tf32 pre-convert (rna), vectorized
// ---------------------------------------------------------------------------
__global__ void cvt_tf32_kernel(const float* __restrict__ src, uint32_t* __restrict__ dst, int n) {
    int i = (blockIdx.x * 256 + threadIdx.x) * 4;
    if (i < n) {
        float4 v = *(const float4*)(src + i);
        uint4 u = { f2tf(v.x), f2tf(v.y), f2tf(v.z), f2tf(v.w) };
        *(uint4*)(dst + i) = u;
    }
}

// ---------------------------------------------------------------------------
// cp.async-pipelined tf32 GEMM: tile 128x128, BK=32, 4 stages, 256 threads.
// A [M,1024] (tf32 bits), B [1024,N] (tf32 bits). Warp tile 32x64.
// As layout [128][36] (row-major, k contig); Bs [32][136] (k rows, n contig).
// MODE 0: QKV scatter + tf32-round; MODE 1: C = acc + bias (fp32).
// ---------------------------------------------------------------------------
#define A_ST 4608        // 128*36 words per stage
#define B_ST 4352        // 32*136 words per stage
#define GSMEM ((4*A_ST + 4*B_ST) * 4)   // 143360 B

__device__ __forceinline__ void g_issue(const uint32_t* A, const uint32_t* B,
                                        int N, int m0, int n0, int t, int tid,
                                        uint32_t sb) {
    const int s = t & 3;
    const uint32_t abase = sb + s * (A_ST * 4);
    const uint32_t bbase = sb + (4 * A_ST + s * B_ST) * 4;
    const uint32_t* ag = A + (size_t)m0 * 1024 + t * 32;
    const uint32_t* bg = B + (size_t)(t * 32) * N + n0;
#pragma unroll
    for (int i = 0; i < 4; i++) {
        const int id = tid + i * 256;
        const int r = id >> 3, c = id & 7;
        CP16(abase + r * 144 + c * 16, ag + (size_t)r * 1024 + c * 4);
        const int kr = id >> 5, nc = id & 31;
        CP16(bbase + kr * 544 + nc * 16, bg + (size_t)kr * N + nc * 4);
    }
    CPCOMMIT();
}

template<int MODE>
__global__ __launch_bounds__(256)
void gemm_cp(const uint32_t* __restrict__ A, const uint32_t* __restrict__ B,
             const float* __restrict__ bias, float* __restrict__ C, int N,
             float* __restrict__ oq, float* __restrict__ ok, float* __restrict__ ov)
{
    extern __shared__ uint32_t sw[];
    const uint32_t sb = smem_u32(sw);

    const int tid  = threadIdx.x;
    const int lane = tid & 31;
    const int wid  = tid >> 5;
    const int g    = lane >> 2;
    const int tg   = lane & 3;
    const int warp_m = (wid & 3) * 32;
    const int warp_n = (wid >> 2) * 64;
    const int m0 = blockIdx.y * 128;
    const int n0 = blockIdx.x * 128;

    float acc[2][8][4];
#pragma unroll
    for (int mt = 0; mt < 2; mt++)
#pragma unroll
        for (int nt = 0; nt < 8; nt++)
#pragma unroll
            for (int i = 0; i < 4; i++) acc[mt][nt][i] = 0.f;

    // prologue: 3 stages in flight
    g_issue(A, B, N, m0, n0, 0, tid, sb);
    g_issue(A, B, N, m0, n0, 1, tid, sb);
    g_issue(A, B, N, m0, n0, 2, tid, sb);

    for (int t = 0; t < 32; ++t) {
        if (t < 30) { CPWAIT(2); }
        else if (t == 30) { CPWAIT(1); }
        else { CPWAIT(0); }
        __syncthreads();

        const uint32_t* As_s = sw + (t & 3) * A_ST;
        const uint32_t* Bs_s = sw + 4 * A_ST + (t & 3) * B_ST;

#pragma unroll
        for (int ks = 0; ks < 4; ++ks) {
            const int kb = ks * 8;
            uint32_t afr[2][4];
#pragma unroll
            for (int mt = 0; mt < 2; mt++) {
                const int r = warp_m + mt * 16 + g;
                afr[mt][0] = As_s[r * 36 + kb + tg];
                afr[mt][1] = As_s[(r + 8) * 36 + kb + tg];
                afr[mt][2] = As_s[r * 36 + kb + tg + 4];
                afr[mt][3] = As_s[(r + 8) * 36 + kb + tg + 4];
            }
            uint32_t bfr[8][2];
#pragma unroll
            for (int nt = 0; nt < 8; nt++) {
                const int c = warp_n + nt * 8 + g;
                bfr[nt][0] = Bs_s[(kb + tg) * 136 + c];
                bfr[nt][1] = Bs_s[(kb + tg + 4) * 136 + c];
            }
#pragma unroll
            for (int mt = 0; mt < 2; mt++)
#pragma unroll
                for (int nt = 0; nt < 8; nt++)
                    mma8(acc[mt][nt], afr[mt], bfr[nt][0], bfr[nt][1]);
        }
        __syncthreads();
        if (t + 3 < 32) g_issue(A, B, N, m0, n0, t + 3, tid, sb);
    }

    // epilogue
    const int rowB = m0 + warp_m;
    const int colB = n0 + warp_n;
#pragma unroll
    for (int mt = 0; mt < 2; mt++) {
#pragma unroll
        for (int nt = 0; nt < 8; nt++) {
            const int r = rowB + mt * 16 + g;
            const int c = colB + nt * 8 + 2 * tg;
            const float bv0 = bias[c], bv1 = bias[c + 1];
            if (MODE == 0) {
                // tf32-round so downstream kernels can cp.async raw bits
                float v00 = __uint_as_float(f2tf(acc[mt][nt][0] + bv0));
                float v01 = __uint_as_float(f2tf(acc[mt][nt][1] + bv1));
                float v10 = __uint_as_float(f2tf(acc[mt][nt][2] + bv0));
                float v11 = __uint_as_float(f2tf(acc[mt][nt][3] + bv1));
                const int sel = c >> 10;
                const int cc  = c & 1023;
                const int h   = cc >> 6;
                const int d   = cc & 63;
                float* dst = (sel == 0) ? oq : (sel == 1) ? ok : ov;
                {
                    const int b_ = r >> 11, t_ = r & 2047;
                    const size_t idx = (((size_t)(b_ * NH + h) * SEQ) + t_) * HD + d;
                    *(float2*)&dst[idx] = make_float2(v00, v01);
                }
                {
                    const int r2 = r + 8;
                    const int b_ = r2 >> 11, t_ = r2 & 2047;
                    const size_t idx = (((size_t)(b_ * NH + h) * SEQ) + t_) * HD + d;
                    *(float2*)&dst[idx] = make_float2(v10, v11);
                }
            } else {
                float v00 = acc[mt][nt][0] + bv0;
                float v01 = acc[mt][nt][1] + bv1;
                float v10 = acc[mt][nt][2] + bv0;
                float v11 = acc[mt][nt][3] + bv1;
                *(float2*)&C[(size_t)r * N + c]       = make_float2(v00, v01);
                *(float2*)&C[(size_t)(r + 8) * N + c] = make_float2(v10, v11);
            }
        }
    }
}

// ---------------------------------------------------------------------------
// Flash attention, tf32 mma, Br=128 x Bc=64, 256 threads (8 warps x 16 rows).
// Inputs already tf32-rounded -> raw cp.async staging. Pad 68 (conflict-free
// for Q/P A-frags, K B-frags, V B-frags). K/V double-buffered cp.async.
// ---------------------------------------------------------------------------
#define ATPAD 68
#define ASMEM ((128*ATPAD + 4*64*ATPAD) * 4)   // 104448 B

__device__ __forceinline__ void issue_kv(const float* k, const float* v,
                                         int bh, int kb, int buf, int tid,
                                         uint32_t kbase, uint32_t vbase) {
    const float* ksrc = k + ((size_t)bh * SEQ + (size_t)kb * 64) * HD;
    const float* vsrc = v + ((size_t)bh * SEQ + (size_t)kb * 64) * HD;
    const uint32_t kb_ = kbase + buf * (64 * ATPAD * 4);
    const uint32_t vb_ = vbase + buf * (64 * ATPAD * 4);
#pragma unroll
    for (int i = 0; i < 4; i++) {
        const int id = tid + i * 256;
        const int r = id >> 4, c = id & 15;
        CP16(kb_ + r * 272 + c * 16, ksrc + (size_t)r * HD + c * 4);
        CP16(vb_ + r * 272 + c * 16, vsrc + (size_t)r * HD + c * 4);
    }
    CPCOMMIT();
}

__global__ __launch_bounds__(256)
void attn_cp(const float* __restrict__ q, const float* __restrict__ k,
             const float* __restrict__ v, float* __restrict__ out)
{
    extern __shared__ uint32_t sw[];
    uint32_t* QP = sw;                       // [128][68], Q then P
    uint32_t* Ks = QP + 128 * ATPAD;         // [2][64][68]
    uint32_t* Vs = Ks + 2 * 64 * ATPAD;      // [2][64][68]
    const uint32_t sb    = smem_u32(sw);
    const uint32_t kbase = sb + 128 * ATPAD * 4;
    const uint32_t vbase = kbase + 2 * 64 * ATPAD * 4;

    const int tid  = threadIdx.x;
    const int lane = tid & 31;
    const int wid  = tid >> 5;
    const int g    = lane >> 2;
    const int tg   = lane & 3;
    const int wbase = wid * 16;

    const int bh = blockIdx.y;
    const int qb = (gridDim.x - 1) - blockIdx.x;   // big tiles first
    const int b_ = bh >> 4;
    const int h  = bh & 15;
    const int nkv = 2 * qb + 2;

    // prologue: G0 = Q + KV0, G1 = KV1 (nkv >= 2 always)
    {
        const float* qsrc = q + ((size_t)bh * SEQ + (size_t)qb * 128) * HD;
#pragma unroll
        for (int i = 0; i < 8; i++) {
            const int id = tid + i * 256;
            const int r = id >> 4, c = id & 15;
            CP16(sb + r * 272 + c * 16, qsrc + (size_t)r * HD + c * 4);
        }
        const float* ksrc = k + ((size_t)bh * SEQ) * HD;
        const float* vsrc = v + ((size_t)bh * SEQ) * HD;
#pragma unroll
        for (int i = 0; i < 4; i++) {
            const int id = tid + i * 256;
            const int r = id >> 4, c = id & 15;
            CP16(kbase + r * 272 + c * 16, ksrc + (size_t)r * HD + c * 4);
            CP16(vbase + r * 272 + c * 16, vsrc + (size_t)r * HD + c * 4);
        }
        CPCOMMIT();
        issue_kv(k, v, bh, 1, 1, tid, kbase, vbase);
    }
    CPWAIT(1);
    __syncthreads();

    // Q fragments (scaled by 1/8, exact for tf32)
    uint32_t qf[8][4];
#pragma unroll
    for (int kt = 0; kt < 8; kt++) {
        const int r0 = wbase + g;
        qf[kt][0] = __float_as_uint(__uint_as_float(QP[r0 * ATPAD + kt * 8 + tg]) * 0.125f);
        qf[kt][1] = __float_as_uint(__uint_as_float(QP[(r0 + 8) * ATPAD + kt * 8 + tg]) * 0.125f);
        qf[kt][2] = __float_as_uint(__uint_as_float(QP[r0 * ATPAD + kt * 8 + tg + 4]) * 0.125f);
        qf[kt][3] = __float_as_uint(__uint_as_float(QP[(r0 + 8) * ATPAD + kt * 8 + tg + 4]) * 0.125f);
    }

    float m0 = -INFINITY, m1 = -INFINITY, l0 = 0.f, l1 = 0.f;
    float O[8][4];
#pragma unroll
    for (int nt = 0; nt < 8; nt++)
#pragma unroll
        for (int i = 0; i < 4; i++) O[nt][i] = 0.f;

    for (int kb = 0; kb < nkv; ++kb) {
        if (kb > 0) {
            if (kb + 1 < nkv) { CPWAIT(1); } else { CPWAIT(0); }
            __syncthreads();
        }
        const uint32_t* Kb = Ks + (kb & 1) * 64 * ATPAD;
        const uint32_t* Vb = Vs + (kb & 1) * 64 * ATPAD;

        // S = Qs @ K^T
        float s_[8][4];
#pragma unroll
        for (int nt = 0; nt < 8; nt++)
#pragma unroll
            for (int i = 0; i < 4; i++) s_[nt][i] = 0.f;
#pragma unroll
        for (int kt = 0; kt < 8; kt++) {
#pragma unroll
            for (int nt = 0; nt < 8; nt++) {
                const int trow = nt * 8 + g;
                uint32_t b0 = Kb[trow * ATPAD + kt * 8 + tg];
                uint32_t b1 = Kb[trow * ATPAD + kt * 8 + tg + 4];
                mma8(s_[nt], qf[kt], b0, b1);
            }
        }

        // causal mask (only possible in the last two kv tiles)
        if (kb >= 2 * qb) {
            const int rg0 = qb * 128 + wbase + g;
#pragma unroll
            for (int nt = 0; nt < 8; nt++) {
                const int cg = kb * 64 + nt * 8 + 2 * tg;
                if (cg > rg0)         s_[nt][0] = -INFINITY;
                if (cg + 1 > rg0)     s_[nt][1] = -INFINITY;
                if (cg > rg0 + 8)     s_[nt][2] = -INFINITY;
                if (cg + 1 > rg0 + 8) s_[nt][3] = -INFINITY;
            }
        }

        // online softmax (rows g, g+8 of this warp's 16-row strip)
        float mx0 = -INFINITY, mx1 = -INFINITY;
#pragma unroll
        for (int nt = 0; nt < 8; nt++) {
            mx0 = fmaxf(mx0, fmaxf(s_[nt][0], s_[nt][1]));
            mx1 = fmaxf(mx1, fmaxf(s_[nt][2], s_[nt][3]));
        }
#pragma unroll
        for (int off = 1; off < 4; off <<= 1) {
            mx0 = fmaxf(mx0, __shfl_xor_sync(0xffffffffu, mx0, off));
            mx1 = fmaxf(mx1, __shfl_xor_sync(0xffffffffu, mx1, off));
        }
        const float mn0 = fmaxf(m0, mx0);
        const float mn1 = fmaxf(m1, mx1);
        const float al0 = __expf(m0 - mn0);
        const float al1 = __expf(m1 - mn1);
        m0 = mn0; m1 = mn1;

        float rs0 = 0.f, rs1 = 0.f;
#pragma unroll
        for (int nt = 0; nt < 8; nt++) {
            s_[nt][0] = __expf(s_[nt][0] - mn0); rs0 += s_[nt][0];
            s_[nt][1] = __expf(s_[nt][1] - mn0); rs0 += s_[nt][1];
            s_[nt][2] = __expf(s_[nt][2] - mn1); rs1 += s_[nt][2];
            s_[nt][3] = __expf(s_[nt][3] - mn1); rs1 += s_[nt][3];
        }
#pragma unroll
        for (int off = 1; off < 4; off <<= 1) {
            rs0 += __shfl_xor_sync(0xffffffffu, rs0, off);
            rs1 += __shfl_xor_sync(0xffffffffu, rs1, off);
        }
        l0 = l0 * al0 + rs0;
        l1 = l1 * al1 + rs1;
#pragma unroll
        for (int nt = 0; nt < 8; nt++) {
            O[nt][0] *= al0; O[nt][1] *= al0;
            O[nt][2] *= al1; O[nt][3] *= al1;
        }

        // P -> QP (own warp's 16 rows only), tf32
#pragma unroll
        for (int nt = 0; nt < 8; nt++) {
            const int rr = wbase + g;
            const int cc = nt * 8 + 2 * tg;
            *(uint2*)&QP[rr * ATPAD + cc]       = make_uint2(f2tf(s_[nt][0]), f2tf(s_[nt][1]));
            *(uint2*)&QP[(rr + 8) * ATPAD + cc] = make_uint2(f2tf(s_[nt][2]), f2tf(s_[nt][3]));
        }
        __syncwarp();

        // O += P @ V
#pragma unroll
        for (int kt = 0; kt < 8; kt++) {
            uint32_t pa[4];
            pa[0] = QP[(wbase + g) * ATPAD + kt * 8 + tg];
            pa[1] = QP[(wbase + g + 8) * ATPAD + kt * 8 + tg];
            pa[2] = QP[(wbase + g) * ATPAD + kt * 8 + tg + 4];
            pa[3] = QP[(wbase + g + 8) * ATPAD + kt * 8 + tg + 4];
#pragma unroll
            for (int nt = 0; nt < 8; nt++) {
                uint32_t b0 = Vb[(kt * 8 + tg) * ATPAD + nt * 8 + g];
                uint32_t b1 = Vb[(kt * 8 + tg + 4) * ATPAD + nt * 8 + g];
                mma8(O[nt], pa, b0, b1);
            }
        }
        __syncthreads();
        if (kb + 2 < nkv) issue_kv(k, v, bh, kb + 2, kb & 1, tid, kbase, vbase);
    }

    // normalize, tf32-round (proj stages raw), write to g_attn [B*T, C]
    const float inv0 = 1.f / l0;
    const float inv1 = 1.f / l1;
    const int t0 = qb * 128 + wbase + g;
#pragma unroll
    for (int nt = 0; nt < 8; nt++) {
        const int c = h * HD + nt * 8 + 2 * tg;
        float2 w0 = { __uint_as_float(f2tf(O[nt][0] * inv0)),
                      __uint_as_float(f2tf(O[nt][1] * inv0)) };
        float2 w1 = { __uint_as_float(f2tf(O[nt][2] * inv1)),
                      __uint_as_float(f2tf(O[nt][3] * inv1)) };
        *(float2*)&out[((size_t)(b_ * SEQ + t0)) * DIM + c]     = w0;
        *(float2*)&out[((size_t)(b_ * SEQ + t0 + 8)) * DIM + c] = w1;
    }
}

// ---------------------------------------------------------------------------
extern "C" void kernel_launch(void* const* d_in, const int* in_sizes, int n_in,
                              void* d_out, int out_size)
{
    const float* x     = (const float*)d_in[0];
    const float* Wqkv  = (const float*)d_in[1];
    const float* bqkv  = (const float*)d_in[2];
    const float* Wproj = (const float*)d_in[3];
    const float* bproj = (const float*)d_in[4];
    float* out = (float*)d_out;

    float *gq, *gk, *gv, *gattn;
    uint32_t *gxt, *gwqkvt, *gwprojt;
    cudaGetSymbolAddress((void**)&gq, g_q);
    cudaGetSymbolAddress((void**)&gk, g_k);
    cudaGetSymbolAddress((void**)&gv, g_v);
    cudaGetSymbolAddress((void**)&gattn, g_attn);
    cudaGetSymbolAddress((void**)&gxt, g_xt);
    cudaGetSymbolAddress((void**)&gwqkvt, g_wqkvt);
    cudaGetSymbolAddress((void**)&gwprojt, g_wprojt);

    cudaFuncSetAttribute(gemm_cp<0>, cudaFuncAttributeMaxDynamicSharedMemorySize, GSMEM);
    cudaFuncSetAttribute(gemm_cp<1>, cudaFuncAttributeMaxDynamicSharedMemorySize, GSMEM);
    cudaFuncSetAttribute(attn_cp,   cudaFuncAttributeMaxDynamicSharedMemorySize, ASMEM);

    // 0) tf32 pre-convert of inputs (rna)
    cvt_tf32_kernel<<<(BT*DIM)/1024, 256>>>(x, gxt, BT*DIM);
    cvt_tf32_kernel<<<(DIM*QKVN)/1024, 256>>>(Wqkv, gwqkvt, DIM*QKVN);
    cvt_tf32_kernel<<<(DIM*DIM)/1024, 256>>>(Wproj, gwprojt, DIM*DIM);

    // 1) QKV projection + head scatter
    {
        dim3 grid(QKVN / 128, BT / 128);   // (24, 32)
        gemm_cp<0><<<grid, 256, GSMEM>>>(gxt, gwqkvt, bqkv, nullptr,
                                         QKVN, gq, gk, gv);
    }
    // 2) Causal flash attention
    {
        dim3 grid(SEQ / 128, BATCH * NH);  // (16, 32)
        attn_cp<<<grid, 256, ASMEM>>>(gq, gk, gv, gattn);
    }
    // 3) Output projection
    {
        dim3 grid(DIM / 128, BT / 128);    // (8, 32)
        gemm_cp<1><<<grid, 256, GSMEM>>>((const uint32_t*)gattn, gwprojt, bproj, out,
                                         DIM, nullptr, nullptr, nullptr);
    }
    (void)in_sizes; (void)n_in; (void)out_size;
}

// round 5
// speedup vs baseline: 3.0157x; 1.0637x over previous
#include <cuda_runtime.h>
#include <math.h>
#include <stdint.h>

#define BATCH 2
#define SEQ   2048
#define DIM   1024
#define NH    16
#define HD    64
#define BT    (BATCH*SEQ)      // 4096
#define QKVN  (3*DIM)          // 3072

// Scratch (static device arrays; no allocations allowed)
__device__ float    g_q[BATCH*NH*SEQ*HD];     // [B,H,T,D]  (tf32-rounded bits)
__device__ float    g_k[BATCH*NH*SEQ*HD];
__device__ float    g_v[BATCH*NH*SEQ*HD];
__device__ float    g_attn[BT*DIM];           // [B*T, C]   (tf32-rounded bits)
__device__ uint32_t g_xt[BT*DIM];             // tf32(x)
__device__ uint32_t g_wqkvt[DIM*QKVN];        // tf32(W_qkv)
__device__ uint32_t g_wprojt[DIM*DIM];        // tf32(W_proj)

// ---------------------------------------------------------------------------
__device__ __forceinline__ uint32_t f2tf(float f) {
    uint32_t u;
    asm("cvt.rna.tf32.f32 %0, %1;" : "=r"(u) : "f"(f));
    return u;
}
__device__ __forceinline__ uint32_t smem_u32(const void* p) {
    uint32_t a;
    asm("{ .reg .u64 t; cvta.to.shared.u64 t, %1; cvt.u32.u64 %0, t; }" : "=r"(a) : "l"(p));
    return a;
}
#define CP16(dst, src) \
    asm volatile("cp.async.cg.shared.global [%0], [%1], 16;" :: "r"(dst), "l"(src) : "memory")
#define CPCOMMIT() asm volatile("cp.async.commit_group;" ::: "memory")
#define CPWAIT(n)  asm volatile("cp.async.wait_group %0;" :: "n"(n) : "memory")

// m16n8k8 tf32 mma, fp32 accum
__device__ __forceinline__ void mma8(float* c, const uint32_t* a, uint32_t b0, uint32_t b1) {
    asm volatile(
        "mma.sync.aligned.m16n8k8.row.col.f32.tf32.tf32.f32 "
        "{%0,%1,%2,%3},{%4,%5,%6,%7},{%8,%9},{%0,%1,%2,%3};\n"
        : "+f"(c[0]), "+f"(c[1]), "+f"(c[2]), "+f"(c[3])
        : "r"(a[0]), "r"(a[1]), "r"(a[2]), "r"(a[3]), "r"(b0), "r"(b1));
}

// ---------------------------------------------------------------------------
// tf32 pre-convert (rna), vectorized
// ---------------------------------------------------------------------------
__global__ void cvt_tf32_kernel(const float* __restrict__ src, uint32_t* __restrict__ dst, int n) {
    int i = (blockIdx.x * 256 + threadIdx.x) * 4;
    if (i < n) {
        float4 v = *(const float4*)(src + i);
        uint4 u = { f2tf(v.x), f2tf(v.y), f2tf(v.z), f2tf(v.w) };
        *(uint4*)(dst + i) = u;
    }
}

// ---------------------------------------------------------------------------
// cp.async-pipelined tf32 GEMM: tile 128x128, BK=32, 3 stages, 256 threads,
// 2 CTAs/SM. One __syncthreads per k-chunk.
// A [M,1024] (tf32 bits), B [1024,N] (tf32 bits). Warp tile 32x64.
// As layout [128][36] (row-major, k contig); Bs [32][136] (k rows, n contig).
// MODE 0: QKV scatter + tf32-round; MODE 1: C = acc + bias (fp32).
// ---------------------------------------------------------------------------
#define A_ST 4608        // 128*36 words per stage
#define B_ST 4352        // 32*136 words per stage
#define GSMEM ((3*A_ST + 3*B_ST) * 4)   // 107520 B -> 2 CTAs/SM

__device__ __forceinline__ void g_issue(const uint32_t* A, const uint32_t* B,
                                        int N, int m0, int n0, int t, int tid,
                                        uint32_t sb) {
    const int s = t % 3;
    const uint32_t abase = sb + s * (A_ST * 4);
    const uint32_t bbase = sb + (3 * A_ST + s * B_ST) * 4;
    const uint32_t* ag = A + (size_t)m0 * 1024 + t * 32;
    const uint32_t* bg = B + (size_t)(t * 32) * N + n0;
#pragma unroll
    for (int i = 0; i < 4; i++) {
        const int id = tid + i * 256;
        const int r = id >> 3, c = id & 7;
        CP16(abase + r * 144 + c * 16, ag + (size_t)r * 1024 + c * 4);
        const int kr = id >> 5, nc = id & 31;
        CP16(bbase + kr * 544 + nc * 16, bg + (size_t)kr * N + nc * 4);
    }
    CPCOMMIT();
}

template<int MODE>
__global__ __launch_bounds__(256, 2)
void gemm_cp(const uint32_t* __restrict__ A, const uint32_t* __restrict__ B,
             const float* __restrict__ bias, float* __restrict__ C, int N,
             float* __restrict__ oq, float* __restrict__ ok, float* __restrict__ ov)
{
    extern __shared__ uint32_t sw[];
    const uint32_t sb = smem_u32(sw);

    const int tid  = threadIdx.x;
    const int lane = tid & 31;
    const int wid  = tid >> 5;
    const int g    = lane >> 2;
    const int tg   = lane & 3;
    const int warp_m = (wid & 3) * 32;
    const int warp_n = (wid >> 2) * 64;
    const int m0 = blockIdx.y * 128;
    const int n0 = blockIdx.x * 128;

    float acc[2][8][4];
#pragma unroll
    for (int mt = 0; mt < 2; mt++)
#pragma unroll
        for (int nt = 0; nt < 8; nt++)
#pragma unroll
            for (int i = 0; i < 4; i++) acc[mt][nt][i] = 0.f;

    // prologue: 2 stages in flight
    g_issue(A, B, N, m0, n0, 0, tid, sb);
    g_issue(A, B, N, m0, n0, 1, tid, sb);

    for (int t = 0; t < 32; ++t) {
        if (t < 31) { CPWAIT(1); } else { CPWAIT(0); }
        __syncthreads();
        // safe: the sync above also proves all warps finished reading stage
        // (t+2)%3 during iteration t-1, so we can overwrite it now.
        if (t + 2 < 32) g_issue(A, B, N, m0, n0, t + 2, tid, sb);

        const uint32_t* As_s = sw + (t % 3) * A_ST;
        const uint32_t* Bs_s = sw + 3 * A_ST + (t % 3) * B_ST;

#pragma unroll
        for (int ks = 0; ks < 4; ++ks) {
            const int kb = ks * 8;
            uint32_t afr[2][4];
#pragma unroll
            for (int mt = 0; mt < 2; mt++) {
                const int r = warp_m + mt * 16 + g;
                afr[mt][0] = As_s[r * 36 + kb + tg];
                afr[mt][1] = As_s[(r + 8) * 36 + kb + tg];
                afr[mt][2] = As_s[r * 36 + kb + tg + 4];
                afr[mt][3] = As_s[(r + 8) * 36 + kb + tg + 4];
            }
            uint32_t bfr[8][2];
#pragma unroll
            for (int nt = 0; nt < 8; nt++) {
                const int c = warp_n + nt * 8 + g;
                bfr[nt][0] = Bs_s[(kb + tg) * 136 + c];
                bfr[nt][1] = Bs_s[(kb + tg + 4) * 136 + c];
            }
#pragma unroll
            for (int mt = 0; mt < 2; mt++)
#pragma unroll
                for (int nt = 0; nt < 8; nt++)
                    mma8(acc[mt][nt], afr[mt], bfr[nt][0], bfr[nt][1]);
        }
    }

    // epilogue
    const int rowB = m0 + warp_m;
    const int colB = n0 + warp_n;
#pragma unroll
    for (int mt = 0; mt < 2; mt++) {
#pragma unroll
        for (int nt = 0; nt < 8; nt++) {
            const int r = rowB + mt * 16 + g;
            const int c = colB + nt * 8 + 2 * tg;
            const float bv0 = bias[c], bv1 = bias[c + 1];
            if (MODE == 0) {
                // tf32-round so downstream kernels can cp.async raw bits
                float v00 = __uint_as_float(f2tf(acc[mt][nt][0] + bv0));
                float v01 = __uint_as_float(f2tf(acc[mt][nt][1] + bv1));
                float v10 = __uint_as_float(f2tf(acc[mt][nt][2] + bv0));
                float v11 = __uint_as_float(f2tf(acc[mt][nt][3] + bv1));
                const int sel = c >> 10;
                const int cc  = c & 1023;
                const int h   = cc >> 6;
                const int d   = cc & 63;
                float* dst = (sel == 0) ? oq : (sel == 1) ? ok : ov;
                {
                    const int b_ = r >> 11, t_ = r & 2047;
                    const size_t idx = (((size_t)(b_ * NH + h) * SEQ) + t_) * HD + d;
                    *(float2*)&dst[idx] = make_float2(v00, v01);
                }
                {
                    const int r2 = r + 8;
                    const int b_ = r2 >> 11, t_ = r2 & 2047;
                    const size_t idx = (((size_t)(b_ * NH + h) * SEQ) + t_) * HD + d;
                    *(float2*)&dst[idx] = make_float2(v10, v11);
                }
            } else {
                float v00 = acc[mt][nt][0] + bv0;
                float v01 = acc[mt][nt][1] + bv1;
                float v10 = acc[mt][nt][2] + bv0;
                float v11 = acc[mt][nt][3] + bv1;
                *(float2*)&C[(size_t)r * N + c]       = make_float2(v00, v01);
                *(float2*)&C[(size_t)(r + 8) * N + c] = make_float2(v10, v11);
            }
        }
    }
}

// ---------------------------------------------------------------------------
// Flash attention, tf32 mma, Br=128 x Bc=64, 256 threads (8 warps x 16 rows).
// Inputs already tf32-rounded -> raw cp.async staging. Pad 68 (conflict-free
// for Q/P A-frags, K B-frags, V B-frags). K/V double-buffered cp.async.
// (unchanged from round 4 — passing)
// ---------------------------------------------------------------------------
#define ATPAD 68
#define ASMEM ((128*ATPAD + 4*64*ATPAD) * 4)   // 104448 B

__device__ __forceinline__ void issue_kv(const float* k, const float* v,
                                         int bh, int kb, int buf, int tid,
                                         uint32_t kbase, uint32_t vbase) {
    const float* ksrc = k + ((size_t)bh * SEQ + (size_t)kb * 64) * HD;
    const float* vsrc = v + ((size_t)bh * SEQ + (size_t)kb * 64) * HD;
    const uint32_t kb_ = kbase + buf * (64 * ATPAD * 4);
    const uint32_t vb_ = vbase + buf * (64 * ATPAD * 4);
#pragma unroll
    for (int i = 0; i < 4; i++) {
        const int id = tid + i * 256;
        const int r = id >> 4, c = id & 15;
        CP16(kb_ + r * 272 + c * 16, ksrc + (size_t)r * HD + c * 4);
        CP16(vb_ + r * 272 + c * 16, vsrc + (size_t)r * HD + c * 4);
    }
    CPCOMMIT();
}

__global__ __launch_bounds__(256)
void attn_cp(const float* __restrict__ q, const float* __restrict__ k,
             const float* __restrict__ v, float* __restrict__ out)
{
    extern __shared__ uint32_t sw[];
    uint32_t* QP = sw;                       // [128][68], Q then P
    uint32_t* Ks = QP + 128 * ATPAD;         // [2][64][68]
    uint32_t* Vs = Ks + 2 * 64 * ATPAD;      // [2][64][68]
    const uint32_t sb    = smem_u32(sw);
    const uint32_t kbase = sb + 128 * ATPAD * 4;
    const uint32_t vbase = kbase + 2 * 64 * ATPAD * 4;

    const int tid  = threadIdx.x;
    const int lane = tid & 31;
    const int wid  = tid >> 5;
    const int g    = lane >> 2;
    const int tg   = lane & 3;
    const int wbase = wid * 16;

    const int bh = blockIdx.y;
    const int qb = (gridDim.x - 1) - blockIdx.x;   // big tiles first
    const int b_ = bh >> 4;
    const int h  = bh & 15;
    const int nkv = 2 * qb + 2;

    // prologue: G0 = Q + KV0, G1 = KV1 (nkv >= 2 always)
    {
        const float* qsrc = q + ((size_t)bh * SEQ + (size_t)qb * 128) * HD;
#pragma unroll
        for (int i = 0; i < 8; i++) {
            const int id = tid + i * 256;
            const int r = id >> 4, c = id & 15;
            CP16(sb + r * 272 + c * 16, qsrc + (size_t)r * HD + c * 4);
        }
        const float* ksrc = k + ((size_t)bh * SEQ) * HD;
        const float* vsrc = v + ((size_t)bh * SEQ) * HD;
#pragma unroll
        for (int i = 0; i < 4; i++) {
            const int id = tid + i * 256;
            const int r = id >> 4, c = id & 15;
            CP16(kbase + r * 272 + c * 16, ksrc + (size_t)r * HD + c * 4);
            CP16(vbase + r * 272 + c * 16, vsrc + (size_t)r * HD + c * 4);
        }
        CPCOMMIT();
        issue_kv(k, v, bh, 1, 1, tid, kbase, vbase);
    }
    CPWAIT(1);
    __syncthreads();

    // Q fragments (scaled by 1/8, exact for tf32)
    uint32_t qf[8][4];
#pragma unroll
    for (int kt = 0; kt < 8; kt++) {
        const int r0 = wbase + g;
        qf[kt][0] = __float_as_uint(__uint_as_float(QP[r0 * ATPAD + kt * 8 + tg]) * 0.125f);
        qf[kt][1] = __float_as_uint(__uint_as_float(QP[(r0 + 8) * ATPAD + kt * 8 + tg]) * 0.125f);
        qf[kt][2] = __float_as_uint(__uint_as_float(QP[r0 * ATPAD + kt * 8 + tg + 4]) * 0.125f);
        qf[kt][3] = __float_as_uint(__uint_as_float(QP[(r0 + 8) * ATPAD + kt * 8 + tg + 4]) * 0.125f);
    }

    float m0 = -INFINITY, m1 = -INFINITY, l0 = 0.f, l1 = 0.f;
    float O[8][4];
#pragma unroll
    for (int nt = 0; nt < 8; nt++)
#pragma unroll
        for (int i = 0; i < 4; i++) O[nt][i] = 0.f;

    for (int kb = 0; kb < nkv; ++kb) {
        if (kb > 0) {
            if (kb + 1 < nkv) { CPWAIT(1); } else { CPWAIT(0); }
            __syncthreads();
        }
        const uint32_t* Kb = Ks + (kb & 1) * 64 * ATPAD;
        const uint32_t* Vb = Vs + (kb & 1) * 64 * ATPAD;

        // S = Qs @ K^T
        float s_[8][4];
#pragma unroll
        for (int nt = 0; nt < 8; nt++)
#pragma unroll
            for (int i = 0; i < 4; i++) s_[nt][i] = 0.f;
#pragma unroll
        for (int kt = 0; kt < 8; kt++) {
#pragma unroll
            for (int nt = 0; nt < 8; nt++) {
                const int trow = nt * 8 + g;
                uint32_t b0 = Kb[trow * ATPAD + kt * 8 + tg];
                uint32_t b1 = Kb[trow * ATPAD + kt * 8 + tg + 4];
                mma8(s_[nt], qf[kt], b0, b1);
            }
        }

        // causal mask (only possible in the last two kv tiles)
        if (kb >= 2 * qb) {
            const int rg0 = qb * 128 + wbase + g;
#pragma unroll
            for (int nt = 0; nt < 8; nt++) {
                const int cg = kb * 64 + nt * 8 + 2 * tg;
                if (cg > rg0)         s_[nt][0] = -INFINITY;
                if (cg + 1 > rg0)     s_[nt][1] = -INFINITY;
                if (cg > rg0 + 8)     s_[nt][2] = -INFINITY;
                if (cg + 1 > rg0 + 8) s_[nt][3] = -INFINITY;
            }
        }

        // online softmax (rows g, g+8 of this warp's 16-row strip)
        float mx0 = -INFINITY, mx1 = -INFINITY;
#pragma unroll
        for (int nt = 0; nt < 8; nt++) {
            mx0 = fmaxf(mx0, fmaxf(s_[nt][0], s_[nt][1]));
            mx1 = fmaxf(mx1, fmaxf(s_[nt][2], s_[nt][3]));
        }
#pragma unroll
        for (int off = 1; off < 4; off <<= 1) {
            mx0 = fmaxf(mx0, __shfl_xor_sync(0xffffffffu, mx0, off));
            mx1 = fmaxf(mx1, __shfl_xor_sync(0xffffffffu, mx1, off));
        }
        const float mn0 = fmaxf(m0, mx0);
        const float mn1 = fmaxf(m1, mx1);
        const float al0 = __expf(m0 - mn0);
        const float al1 = __expf(m1 - mn1);
        m0 = mn0; m1 = mn1;

        float rs0 = 0.f, rs1 = 0.f;
#pragma unroll
        for (int nt = 0; nt < 8; nt++) {
            s_[nt][0] = __expf(s_[nt][0] - mn0); rs0 += s_[nt][0];
            s_[nt][1] = __expf(s_[nt][1] - mn0); rs0 += s_[nt][1];
            s_[nt][2] = __expf(s_[nt][2] - mn1); rs1 += s_[nt][2];
            s_[nt][3] = __expf(s_[nt][3] - mn1); rs1 += s_[nt][3];
        }
#pragma unroll
        for (int off = 1; off < 4; off <<= 1) {
            rs0 += __shfl_xor_sync(0xffffffffu, rs0, off);
            rs1 += __shfl_xor_sync(0xffffffffu, rs1, off);
        }
        l0 = l0 * al0 + rs0;
        l1 = l1 * al1 + rs1;
#pragma unroll
        for (int nt = 0; nt < 8; nt++) {
            O[nt][0] *= al0; O[nt][1] *= al0;
            O[nt][2] *= al1; O[nt][3] *= al1;
        }

        // P -> QP (own warp's 16 rows only), tf32
#pragma unroll
        for (int nt = 0; nt < 8; nt++) {
            const int rr = wbase + g;
            const int cc = nt * 8 + 2 * tg;
            *(uint2*)&QP[rr * ATPAD + cc]       = make_uint2(f2tf(s_[nt][0]), f2tf(s_[nt][1]));
            *(uint2*)&QP[(rr + 8) * ATPAD + cc] = make_uint2(f2tf(s_[nt][2]), f2tf(s_[nt][3]));
        }
        __syncwarp();

        // O += P @ V
#pragma unroll
        for (int kt = 0; kt < 8; kt++) {
            uint32_t pa[4];
            pa[0] = QP[(wbase + g) * ATPAD + kt * 8 + tg];
            pa[1] = QP[(wbase + g + 8) * ATPAD + kt * 8 + tg];
            pa[2] = QP[(wbase + g) * ATPAD + kt * 8 + tg + 4];
            pa[3] = QP[(wbase + g + 8) * ATPAD + kt * 8 + tg + 4];
#pragma unroll
            for (int nt = 0; nt < 8; nt++) {
                uint32_t b0 = Vb[(kt * 8 + tg) * ATPAD + nt * 8 + g];
                uint32_t b1 = Vb[(kt * 8 + tg + 4) * ATPAD + nt * 8 + g];
                mma8(O[nt], pa, b0, b1);
            }
        }
        __syncthreads();
        if (kb + 2 < nkv) issue_kv(k, v, bh, kb + 2, kb & 1, tid, kbase, vbase);
    }

    // normalize, tf32-round (proj stages raw), write to g_attn [B*T, C]
    const float inv0 = 1.f / l0;
    const float inv1 = 1.f / l1;
    const int t0 = qb * 128 + wbase + g;
#pragma unroll
    for (int nt = 0; nt < 8; nt++) {
        const int c = h * HD + nt * 8 + 2 * tg;
        float2 w0 = { __uint_as_float(f2tf(O[nt][0] * inv0)),
                      __uint_as_float(f2tf(O[nt][1] * inv0)) };
        float2 w1 = { __uint_as_float(f2tf(O[nt][2] * inv1)),
                      __uint_as_float(f2tf(O[nt][3] * inv1)) };
        *(float2*)&out[((size_t)(b_ * SEQ + t0)) * DIM + c]     = w0;
        *(float2*)&out[((size_t)(b_ * SEQ + t0 + 8)) * DIM + c] = w1;
    }
}

// ---------------------------------------------------------------------------
extern "C" void kernel_launch(void* const* d_in, const int* in_sizes, int n_in,
                              void* d_out, int out_size)
{
    const float* x     = (const float*)d_in[0];
    const float* Wqkv  = (const float*)d_in[1];
    const float* bqkv  = (const float*)d_in[2];
    const float* Wproj = (const float*)d_in[3];
    const float* bproj = (const float*)d_in[4];
    float* out = (float*)d_out;

    float *gq, *gk, *gv, *gattn;
    uint32_t *gxt, *gwqkvt, *gwprojt;
    cudaGetSymbolAddress((void**)&gq, g_q);
    cudaGetSymbolAddress((void**)&gk, g_k);
    cudaGetSymbolAddress((void**)&gv, g_v);
    cudaGetSymbolAddress((void**)&gattn, g_attn);
    cudaGetSymbolAddress((void**)&gxt, g_xt);
    cudaGetSymbolAddress((void**)&gwqkvt, g_wqkvt);
    cudaGetSymbolAddress((void**)&gwprojt, g_wprojt);

    cudaFuncSetAttribute(gemm_cp<0>, cudaFuncAttributeMaxDynamicSharedMemorySize, GSMEM);
    cudaFuncSetAttribute(gemm_cp<1>, cudaFuncAttributeMaxDynamicSharedMemorySize, GSMEM);
    cudaFuncSetAttribute(attn_cp,   cudaFuncAttributeMaxDynamicSharedMemorySize, ASMEM);

    // 0) tf32 pre-convert of inputs (rna)
    cvt_tf32_kernel<<<(BT*DIM)/1024, 256>>>(x, gxt, BT*DIM);
    cvt_tf32_kernel<<<(DIM*QKVN)/1024, 256>>>(Wqkv, gwqkvt, DIM*QKVN);
    cvt_tf32_kernel<<<(DIM*DIM)/1024, 256>>>(Wproj, gwprojt, DIM*DIM);

    // 1) QKV projection + head scatter
    {
        dim3 grid(QKVN / 128, BT / 128);   // (24, 32)
        gemm_cp<0><<<grid, 256, GSMEM>>>(gxt, gwqkvt, bqkv, nullptr,
                                         QKVN, gq, gk, gv);
    }
    // 2) Causal flash attention
    {
        dim3 grid(SEQ / 128, BATCH * NH);  // (16, 32)
        attn_cp<<<grid, 256, ASMEM>>>(gq, gk, gv, gattn);
    }
    // 3) Output projection
    {
        dim3 grid(DIM / 128, BT / 128);    // (8, 32)
        gemm_cp<1><<<grid, 256, GSMEM>>>((const uint32_t*)gattn, gwprojt, bproj, out,
                                         DIM, nullptr, nullptr, nullptr);
    }
    (void)in_sizes; (void)n_in; (void)out_size;
}

// round 6
// speedup vs baseline: 5.2698x; 1.7475x over previous
#include <cuda_runtime.h>
#include <cuda_fp16.h>
#include <math.h>
#include <stdint.h>

#define BATCH 2
#define SEQ   2048
#define DIM   1024
#define NH    16
#define HD    64
#define BT    (BATCH*SEQ)      // 4096
#define QKVN  (3*DIM)          // 3072

// Scratch (static device arrays; no allocations allowed)
__device__ __half g_q[BATCH*NH*SEQ*HD];     // [B,H,T,D]
__device__ __half g_k[BATCH*NH*SEQ*HD];     // [B,H,T,D]
__device__ __half g_vt[BATCH*NH*HD*SEQ];    // [B,H,D,T]  (transposed V)
__device__ __half g_attn[BT*DIM];           // [B*T, C]
__device__ __half g_xh[BT*DIM];             // fp16(x)
__device__ __half g_wqkvh[QKVN*DIM];        // fp16(W_qkv^T)  [N][K]
__device__ __half g_wprojh[DIM*DIM];        // fp16(W_proj^T) [N][K]

// ---------------------------------------------------------------------------
__device__ __forceinline__ uint32_t smem_u32(const void* p) {
    uint32_t a;
    asm("{ .reg .u64 t; cvta.to.shared.u64 t, %1; cvt.u32.u64 %0, t; }" : "=r"(a) : "l"(p));
    return a;
}
__device__ __forceinline__ uint32_t pack_h2(float lo, float hi) {
    __half2 h = __floats2half2_rn(lo, hi);
    return *reinterpret_cast<uint32_t*>(&h);
}
#define CP16(dst, src) \
    asm volatile("cp.async.cg.shared.global [%0], [%1], 16;" :: "r"(dst), "l"(src) : "memory")
#define CPCOMMIT() asm volatile("cp.async.commit_group;" ::: "memory")
#define CPWAIT(n)  asm volatile("cp.async.wait_group %0;" :: "n"(n) : "memory")

// m16n8k16 fp16 mma, fp32 accum
__device__ __forceinline__ void mma16(float* c, const uint32_t* a, uint32_t b0, uint32_t b1) {
    asm volatile(
        "mma.sync.aligned.m16n8k16.row.col.f32.f16.f16.f32 "
        "{%0,%1,%2,%3},{%4,%5,%6,%7},{%8,%9},{%0,%1,%2,%3};\n"
        : "+f"(c[0]), "+f"(c[1]), "+f"(c[2]), "+f"(c[3])
        : "r"(a[0]), "r"(a[1]), "r"(a[2]), "r"(a[3]), "r"(b0), "r"(b1));
}

// ---------------------------------------------------------------------------
// pre-convert kernels
// ---------------------------------------------------------------------------
__global__ void cvt_h_kernel(const float* __restrict__ src, __half* __restrict__ dst, int n) {
    int i = (blockIdx.x * 256 + threadIdx.x) * 8;
    if (i < n) {
        float4 v0 = *(const float4*)(src + i);
        float4 v1 = *(const float4*)(src + i + 4);
        uint4 u = { pack_h2(v0.x, v0.y), pack_h2(v0.z, v0.w),
                    pack_h2(v1.x, v1.y), pack_h2(v1.z, v1.w) };
        *(uint4*)(dst + i) = u;
    }
}

// src [K][N] fp32 row-major -> dst [N][K] fp16
__global__ void cvt_tr_kernel(const float* __restrict__ src, __half* __restrict__ dst,
                              int K, int N) {
    __shared__ float tile[32][33];
    const int n0 = blockIdx.x * 32, k0 = blockIdx.y * 32;
    const int tx = threadIdx.x, ty = threadIdx.y;
    for (int i = ty; i < 32; i += 8)
        tile[i][tx] = src[(size_t)(k0 + i) * N + n0 + tx];
    __syncthreads();
    for (int i = ty; i < 32; i += 8)
        dst[(size_t)(n0 + i) * K + k0 + tx] = __float2half_rn(tile[tx][i]);
}

// ---------------------------------------------------------------------------
// cp.async-pipelined fp16 GEMM: tile 128x128, BK=32, 3 stages, 256 threads,
// 2 CTAs/SM, m16n8k16. A [M,1024] fp16 row-major; B pre-transposed [N][1024]
// fp16 (k-contiguous). Smem: A [128][40] halfs, B [128][40] halfs per stage
// (stride 80 B -> conflict-free fragment loads).
// MODE 0: QKV scatter (q,k normal; v transposed) ; MODE 1: C = acc + bias.
// ---------------------------------------------------------------------------
#define GST 2560                       // words (uint32) per A or B stage: 128*40/2
#define GSMEM (6 * GST * 4)            // 61440 B -> 2 CTAs/SM

__device__ __forceinline__ void g_issue(const __half* A, const __half* Bt,
                                        int m0, int n0, int t, int tid, uint32_t sb) {
    const int s = t % 3;
    const uint32_t abase = sb + s * (GST * 4);
    const uint32_t bbase = sb + (3 + s) * (GST * 4);
#pragma unroll
    for (int i = 0; i < 2; i++) {
        const int id = tid + i * 256;
        const int r = id >> 2, c = id & 3;
        CP16(abase + r * 80 + c * 16, A  + (size_t)(m0 + r) * 1024 + t * 32 + c * 8);
        CP16(bbase + r * 80 + c * 16, Bt + (size_t)(n0 + r) * 1024 + t * 32 + c * 8);
    }
    CPCOMMIT();
}

template<int MODE>
__global__ __launch_bounds__(256, 2)
void gemm_h(const __half* __restrict__ A, const __half* __restrict__ Bt,
            const float* __restrict__ bias, float* __restrict__ C, int N,
            __half* __restrict__ oq, __half* __restrict__ ok, __half* __restrict__ ovt)
{
    extern __shared__ uint32_t sw[];
    const uint32_t sb = smem_u32(sw);

    const int tid  = threadIdx.x;
    const int lane = tid & 31;
    const int wid  = tid >> 5;
    const int g    = lane >> 2;
    const int tg   = lane & 3;
    const int warp_m = (wid & 3) * 32;
    const int warp_n = (wid >> 2) * 64;
    const int m0 = blockIdx.y * 128;
    const int n0 = blockIdx.x * 128;

    float acc[2][8][4];
#pragma unroll
    for (int mt = 0; mt < 2; mt++)
#pragma unroll
        for (int nt = 0; nt < 8; nt++)
#pragma unroll
            for (int i = 0; i < 4; i++) acc[mt][nt][i] = 0.f;

    g_issue(A, Bt, m0, n0, 0, tid, sb);
    g_issue(A, Bt, m0, n0, 1, tid, sb);

    for (int t = 0; t < 32; ++t) {
        if (t < 31) { CPWAIT(1); } else { CPWAIT(0); }
        __syncthreads();
        if (t + 2 < 32) g_issue(A, Bt, m0, n0, t + 2, tid, sb);

        const uint32_t* As_s = sw + (t % 3) * GST;
        const uint32_t* Bs_s = sw + (3 + t % 3) * GST;

#pragma unroll
        for (int ks = 0; ks < 2; ++ks) {
            uint32_t afr[2][4];
#pragma unroll
            for (int mt = 0; mt < 2; mt++) {
                const int r = warp_m + mt * 16 + g;
                afr[mt][0] = As_s[r * 20 + ks * 8 + tg];
                afr[mt][1] = As_s[(r + 8) * 20 + ks * 8 + tg];
                afr[mt][2] = As_s[r * 20 + ks * 8 + tg + 4];
                afr[mt][3] = As_s[(r + 8) * 20 + ks * 8 + tg + 4];
            }
            uint32_t bfr[8][2];
#pragma unroll
            for (int nt = 0; nt < 8; nt++) {
                const int c = warp_n + nt * 8 + g;
                bfr[nt][0] = Bs_s[c * 20 + ks * 8 + tg];
                bfr[nt][1] = Bs_s[c * 20 + ks * 8 + tg + 4];
            }
#pragma unroll
            for (int mt = 0; mt < 2; mt++)
#pragma unroll
                for (int nt = 0; nt < 8; nt++)
                    mma16(acc[mt][nt], afr[mt], bfr[nt][0], bfr[nt][1]);
        }
    }

    // epilogue
    const int rowB = m0 + warp_m;
    const int colB = n0 + warp_n;
#pragma unroll
    for (int mt = 0; mt < 2; mt++) {
#pragma unroll
        for (int nt = 0; nt < 8; nt++) {
            const int r = rowB + mt * 16 + g;
            const int c = colB + nt * 8 + 2 * tg;
            const float bv0 = bias[c], bv1 = bias[c + 1];
            const float v00 = acc[mt][nt][0] + bv0;
            const float v01 = acc[mt][nt][1] + bv1;
            const float v10 = acc[mt][nt][2] + bv0;
            const float v11 = acc[mt][nt][3] + bv1;
            if (MODE == 0) {
                const int sel = c >> 10;
                const int cc  = c & 1023;
                const int h   = cc >> 6;
                const int d   = cc & 63;
                const int b0_ = r >> 11,        t0_ = r & 2047;
                const int b1_ = (r + 8) >> 11,  t1_ = (r + 8) & 2047;
                if (sel < 2) {
                    __half* dst = (sel == 0) ? oq : ok;
                    const size_t i0 = (((size_t)(b0_ * NH + h) * SEQ) + t0_) * HD + d;
                    const size_t i1 = (((size_t)(b1_ * NH + h) * SEQ) + t1_) * HD + d;
                    *(uint32_t*)&dst[i0] = pack_h2(v00, v01);
                    *(uint32_t*)&dst[i1] = pack_h2(v10, v11);
                } else {
                    // V transposed: [B,H,D,T]
                    const size_t base0 = ((size_t)(b0_ * NH + h) * HD + d) * SEQ + t0_;
                    const size_t base1 = ((size_t)(b1_ * NH + h) * HD + d) * SEQ + t1_;
                    ovt[base0]       = __float2half_rn(v00);
                    ovt[base0 + SEQ] = __float2half_rn(v01);
                    ovt[base1]       = __float2half_rn(v10);
                    ovt[base1 + SEQ] = __float2half_rn(v11);
                }
            } else {
                *(float2*)&C[(size_t)r * N + c]       = make_float2(v00, v01);
                *(float2*)&C[(size_t)(r + 8) * N + c] = make_float2(v10, v11);
            }
        }
    }
}

// ---------------------------------------------------------------------------
// Flash attention, fp16 m16n8k16, Br=128 x Bc=64, 256 threads (8 warps x 16
// rows), 2 CTAs/SM. K [t][d], V transposed [d][t]. Smem stride 72 halfs
// (144 B, conflict-free). QP buffer reused for P (fp16).
// ---------------------------------------------------------------------------
#define AST 4608                       // words per region: 128*36 (QP) = 2*64*36 (K/V)
#define ASMEM (3 * AST * 4)            // 55296 B -> 2 CTAs/SM

__device__ __forceinline__ void issue_kv(const __half* k, const __half* vt,
                                         int bh, int kb, int buf, int tid,
                                         uint32_t kbase, uint32_t vbase) {
    const __half* ksrc = k  + ((size_t)bh * SEQ + (size_t)kb * 64) * HD;
    const __half* vsrc = vt + (size_t)bh * HD * SEQ + (size_t)kb * 64;
    const uint32_t kb_ = kbase + buf * (64 * 144);
    const uint32_t vb_ = vbase + buf * (64 * 144);
#pragma unroll
    for (int i = 0; i < 2; i++) {
        const int id = tid + i * 256;
        const int r = id >> 3, c = id & 7;
        CP16(kb_ + r * 144 + c * 16, ksrc + (size_t)r * HD + c * 8);
        CP16(vb_ + r * 144 + c * 16, vsrc + (size_t)r * SEQ + c * 8);
    }
    CPCOMMIT();
}

__global__ __launch_bounds__(256, 2)
void attn_h(const __half* __restrict__ q, const __half* __restrict__ k,
            const __half* __restrict__ vt, __half* __restrict__ out)
{
    extern __shared__ uint32_t sw[];
    uint32_t* QPw = sw;                    // [128][36] words (Q then P)
    const uint32_t sb    = smem_u32(sw);
    const uint32_t kbase = sb + AST * 4;
    const uint32_t vbase = sb + 2 * AST * 4;
    const uint32_t* Kw  = sw + AST;        // [2][64][36]
    const uint32_t* Vtw = sw + 2 * AST;    // [2][64][36]

    const int tid  = threadIdx.x;
    const int lane = tid & 31;
    const int wid  = tid >> 5;
    const int g    = lane >> 2;
    const int tg   = lane & 3;
    const int wbase = wid * 16;

    const int bh = blockIdx.y;
    const int qb = (gridDim.x - 1) - blockIdx.x;   // big tiles first
    const int b_ = bh >> 4;
    const int h  = bh & 15;
    const int nkv = 2 * qb + 2;

    // prologue: G0 = Q + KV0, G1 = KV1
    {
        const __half* qsrc = q + ((size_t)bh * SEQ + (size_t)qb * 128) * HD;
#pragma unroll
        for (int i = 0; i < 4; i++) {
            const int id = tid + i * 256;
            const int r = id >> 3, c = id & 7;
            CP16(sb + r * 144 + c * 16, qsrc + (size_t)r * HD + c * 8);
        }
        const __half* ksrc = k  + (size_t)bh * SEQ * HD;
        const __half* vsrc = vt + (size_t)bh * HD * SEQ;
#pragma unroll
        for (int i = 0; i < 2; i++) {
            const int id = tid + i * 256;
            const int r = id >> 3, c = id & 7;
            CP16(kbase + r * 144 + c * 16, ksrc + (size_t)r * HD + c * 8);
            CP16(vbase + r * 144 + c * 16, vsrc + (size_t)r * SEQ + c * 8);
        }
        CPCOMMIT();
        issue_kv(k, vt, bh, 1, 1, tid, kbase, vbase);
    }
    CPWAIT(1);
    __syncthreads();

    // Q fragments in registers: 4 ksteps of k16
    uint32_t qf[4][4];
#pragma unroll
    for (int kt = 0; kt < 4; kt++) {
        const int r0 = wbase + g;
        qf[kt][0] = QPw[r0 * 36 + kt * 8 + tg];
        qf[kt][1] = QPw[(r0 + 8) * 36 + kt * 8 + tg];
        qf[kt][2] = QPw[r0 * 36 + kt * 8 + tg + 4];
        qf[kt][3] = QPw[(r0 + 8) * 36 + kt * 8 + tg + 4];
    }

    float m0 = -INFINITY, m1 = -INFINITY, l0 = 0.f, l1 = 0.f;
    float O[8][4];
#pragma unroll
    for (int nt = 0; nt < 8; nt++)
#pragma unroll
        for (int i = 0; i < 4; i++) O[nt][i] = 0.f;

    for (int kb = 0; kb < nkv; ++kb) {
        if (kb > 0) {
            if (kb + 1 < nkv) { CPWAIT(1); } else { CPWAIT(0); }
            __syncthreads();
        }
        const uint32_t* Kb = Kw  + (kb & 1) * 64 * 36;
        const uint32_t* Vb = Vtw + (kb & 1) * 64 * 36;

        // S = Q @ K^T  (then scale by 1/8)
        float s_[8][4];
#pragma unroll
        for (int nt = 0; nt < 8; nt++)
#pragma unroll
            for (int i = 0; i < 4; i++) s_[nt][i] = 0.f;
#pragma unroll
        for (int kt = 0; kt < 4; kt++) {
#pragma unroll
            for (int nt = 0; nt < 8; nt++) {
                const int trow = nt * 8 + g;
                uint32_t b0 = Kb[trow * 36 + kt * 8 + tg];
                uint32_t b1 = Kb[trow * 36 + kt * 8 + tg + 4];
                mma16(s_[nt], qf[kt], b0, b1);
            }
        }
#pragma unroll
        for (int nt = 0; nt < 8; nt++)
#pragma unroll
            for (int i = 0; i < 4; i++) s_[nt][i] *= 0.125f;

        // causal mask (only in the last two kv tiles)
        if (kb >= 2 * qb) {
            const int rg0 = qb * 128 + wbase + g;
#pragma unroll
            for (int nt = 0; nt < 8; nt++) {
                const int cg = kb * 64 + nt * 8 + 2 * tg;
                if (cg > rg0)         s_[nt][0] = -INFINITY;
                if (cg + 1 > rg0)     s_[nt][1] = -INFINITY;
                if (cg > rg0 + 8)     s_[nt][2] = -INFINITY;
                if (cg + 1 > rg0 + 8) s_[nt][3] = -INFINITY;
            }
        }

        // online softmax
        float mx0 = -INFINITY, mx1 = -INFINITY;
#pragma unroll
        for (int nt = 0; nt < 8; nt++) {
            mx0 = fmaxf(mx0, fmaxf(s_[nt][0], s_[nt][1]));
            mx1 = fmaxf(mx1, fmaxf(s_[nt][2], s_[nt][3]));
        }
#pragma unroll
        for (int off = 1; off < 4; off <<= 1) {
            mx0 = fmaxf(mx0, __shfl_xor_sync(0xffffffffu, mx0, off));
            mx1 = fmaxf(mx1, __shfl_xor_sync(0xffffffffu, mx1, off));
        }
        const float mn0 = fmaxf(m0, mx0);
        const float mn1 = fmaxf(m1, mx1);
        const float al0 = __expf(m0 - mn0);
        const float al1 = __expf(m1 - mn1);
        m0 = mn0; m1 = mn1;

        float rs0 = 0.f, rs1 = 0.f;
#pragma unroll
        for (int nt = 0; nt < 8; nt++) {
            s_[nt][0] = __expf(s_[nt][0] - mn0); rs0 += s_[nt][0];
            s_[nt][1] = __expf(s_[nt][1] - mn0); rs0 += s_[nt][1];
            s_[nt][2] = __expf(s_[nt][2] - mn1); rs1 += s_[nt][2];
            s_[nt][3] = __expf(s_[nt][3] - mn1); rs1 += s_[nt][3];
        }
#pragma unroll
        for (int off = 1; off < 4; off <<= 1) {
            rs0 += __shfl_xor_sync(0xffffffffu, rs0, off);
            rs1 += __shfl_xor_sync(0xffffffffu, rs1, off);
        }
        l0 = l0 * al0 + rs0;
        l1 = l1 * al1 + rs1;
#pragma unroll
        for (int nt = 0; nt < 8; nt++) {
            O[nt][0] *= al0; O[nt][1] *= al0;
            O[nt][2] *= al1; O[nt][3] *= al1;
        }

        // P -> QP (own warp's 16 rows only), fp16 pairs
#pragma unroll
        for (int nt = 0; nt < 8; nt++) {
            const int rr = wbase + g;
            QPw[rr * 36 + nt * 4 + tg]       = pack_h2(s_[nt][0], s_[nt][1]);
            QPw[(rr + 8) * 36 + nt * 4 + tg] = pack_h2(s_[nt][2], s_[nt][3]);
        }
        __syncwarp();

        // O += P @ V   (B = V^T [d][t], k-contiguous)
#pragma unroll
        for (int kt = 0; kt < 4; kt++) {
            uint32_t pa[4];
            pa[0] = QPw[(wbase + g) * 36 + kt * 8 + tg];
            pa[1] = QPw[(wbase + g + 8) * 36 + kt * 8 + tg];
            pa[2] = QPw[(wbase + g) * 36 + kt * 8 + tg + 4];
            pa[3] = QPw[(wbase + g + 8) * 36 + kt * 8 + tg + 4];
#pragma unroll
            for (int nt = 0; nt < 8; nt++) {
                const int dcol = nt * 8 + g;
                uint32_t b0 = Vb[dcol * 36 + kt * 8 + tg];
                uint32_t b1 = Vb[dcol * 36 + kt * 8 + tg + 4];
                mma16(O[nt], pa, b0, b1);
            }
        }
        __syncthreads();
        if (kb + 2 < nkv) issue_kv(k, vt, bh, kb + 2, kb & 1, tid, kbase, vbase);
    }

    // normalize, write fp16 to g_attn [B*T, C]
    const float inv0 = 1.f / l0;
    const float inv1 = 1.f / l1;
    const int t0 = qb * 128 + wbase + g;
#pragma unroll
    for (int nt = 0; nt < 8; nt++) {
        const int c = h * HD + nt * 8 + 2 * tg;
        *(uint32_t*)&out[((size_t)(b_ * SEQ + t0)) * DIM + c] =
            pack_h2(O[nt][0] * inv0, O[nt][1] * inv0);
        *(uint32_t*)&out[((size_t)(b_ * SEQ + t0 + 8)) * DIM + c] =
            pack_h2(O[nt][2] * inv1, O[nt][3] * inv1);
    }
}

// ---------------------------------------------------------------------------
extern "C" void kernel_launch(void* const* d_in, const int* in_sizes, int n_in,
                              void* d_out, int out_size)
{
    const float* x     = (const float*)d_in[0];
    const float* Wqkv  = (const float*)d_in[1];
    const float* bqkv  = (const float*)d_in[2];
    const float* Wproj = (const float*)d_in[3];
    const float* bproj = (const float*)d_in[4];
    float* out = (float*)d_out;

    __half *gq, *gk, *gvt, *gattn, *gxh, *gwqkvh, *gwprojh;
    cudaGetSymbolAddress((void**)&gq, g_q);
    cudaGetSymbolAddress((void**)&gk, g_k);
    cudaGetSymbolAddress((void**)&gvt, g_vt);
    cudaGetSymbolAddress((void**)&gattn, g_attn);
    cudaGetSymbolAddress((void**)&gxh, g_xh);
    cudaGetSymbolAddress((void**)&gwqkvh, g_wqkvh);
    cudaGetSymbolAddress((void**)&gwprojh, g_wprojh);

    cudaFuncSetAttribute(gemm_h<0>, cudaFuncAttributeMaxDynamicSharedMemorySize, GSMEM);
    cudaFuncSetAttribute(gemm_h<1>, cudaFuncAttributeMaxDynamicSharedMemorySize, GSMEM);
    cudaFuncSetAttribute(attn_h,   cudaFuncAttributeMaxDynamicSharedMemorySize, ASMEM);

    // 0) fp16 pre-convert (x elementwise; weights converted + transposed to [N][K])
    cvt_h_kernel<<<(BT*DIM)/2048, 256>>>(x, gxh, BT*DIM);
    cvt_tr_kernel<<<dim3(QKVN/32, DIM/32), dim3(32, 8)>>>(Wqkv, gwqkvh, DIM, QKVN);
    cvt_tr_kernel<<<dim3(DIM/32, DIM/32), dim3(32, 8)>>>(Wproj, gwprojh, DIM, DIM);

    // 1) QKV projection + head scatter (V transposed)
    {
        dim3 grid(QKVN / 128, BT / 128);   // (24, 32)
        gemm_h<0><<<grid, 256, GSMEM>>>(gxh, gwqkvh, bqkv, nullptr,
                                        QKVN, gq, gk, gvt);
    }
    // 2) Causal flash attention
    {
        dim3 grid(SEQ / 128, BATCH * NH);  // (16, 32)
        attn_h<<<grid, 256, ASMEM>>>(gq, gk, gvt, gattn);
    }
    // 3) Output projection
    {
        dim3 grid(DIM / 128, BT / 128);    // (8, 32)
        gemm_h<1><<<grid, 256, GSMEM>>>(gattn, gwprojh, bproj, out,
                                        DIM, nullptr, nullptr, nullptr);
    }
    (void)in_sizes; (void)n_in; (void)out_size;
}